// round 14
// baseline (speedup 1.0000x reference)
#include <cuda_runtime.h>
#include <cuda_fp16.h>
#include <cstdint>
#include <cstddef>

#define HID 512
#define EDIM 64
#define BN_EPS 1e-5f
#define MAXN 50000
#define MAXN2 50048
#define MAXE 400000

// ---------------------------------------------------------------------------
// Scratch (device globals; allocation in kernel_launch is forbidden)
__device__ float g_aggr[MAXN * HID];
__device__ float g_h1[MAXN2 * 2 * HID];
__device__ float g_h2[MAXN * HID];
__device__ float g_stats1[4 * HID];
__device__ float g_stats2[2 * HID];
__device__ float g_bnp1[4 * HID];
__device__ float g_bnp2[2 * HID];
__device__ __half g_w1t[2 * HID * HID];     // [1024][512] K-major fp16
__device__ __half g_w2t[HID * 2 * HID];     // [512][1024] K-major fp16
__device__ __half g_wet[HID * EDIM];        // [512][64]  K-major fp16
__device__ __half g_cmb_hi[MAXN2 * HID];    // GEMM1 A pre-split
__device__ __half g_cmb_lo[MAXN2 * HID];
__device__ __half g_h1s_hi[MAXN2 * 2 * HID];// GEMM2 A pre-split
__device__ __half g_h1s_lo[MAXN2 * 2 * HID];

// ---------------------------------------------------------------------------
__global__ void zero_kernel(float* __restrict__ p, int n) {
    int i = blockIdx.x * blockDim.x + threadIdx.x;
    int stride = gridDim.x * blockDim.x;
    for (; i < n; i += stride) p[i] = 0.0f;
}
__global__ void zero4_kernel(float4* __restrict__ p, int n4) {
    int i = blockIdx.x * blockDim.x + threadIdx.x;
    int stride = gridDim.x * blockDim.x;
    float4 z = make_float4(0.f, 0.f, 0.f, 0.f);
    for (; i < n4; i += stride) p[i] = z;
}

// ---------------------------------------------------------------------------
__device__ __forceinline__ uint32_t smem_u32(const void* p) {
    uint32_t a;
    asm("{ .reg .u64 t; cvta.to.shared.u64 t, %1; cvt.u32.u64 %0, t; }" : "=r"(a) : "l"(p));
    return a;
}
__device__ __forceinline__ uint32_t pack2h(float a, float b) {
    return (uint32_t)__half_as_ushort(__float2half_rn(a))
         | ((uint32_t)__half_as_ushort(__float2half_rn(b)) << 16);
}
__device__ __forceinline__ void split2h(float a, float b, uint32_t& hw, uint32_t& lw) {
    __half ha = __float2half_rn(a), hb = __float2half_rn(b);
    float ra = a - __half2float(ha), rb = b - __half2float(hb);
    hw = (uint32_t)__half_as_ushort(ha) | ((uint32_t)__half_as_ushort(hb) << 16);
    lw = pack2h(ra, rb);
}
__device__ __forceinline__ void mma_f16(float c[4], const uint32_t a[4], const uint32_t b[2]) {
    asm volatile(
        "mma.sync.aligned.m16n8k16.row.col.f32.f16.f16.f32 "
        "{%0,%1,%2,%3}, {%4,%5,%6,%7}, {%8,%9}, {%0,%1,%2,%3};\n"
        : "+f"(c[0]), "+f"(c[1]), "+f"(c[2]), "+f"(c[3])
        : "r"(a[0]), "r"(a[1]), "r"(a[2]), "r"(a[3]), "r"(b[0]), "r"(b[1]));
}
__device__ __forceinline__ void ldm_x4(uint32_t r[4], uint32_t addr) {
    asm volatile("ldmatrix.sync.aligned.m8n8.x4.shared.b16 {%0,%1,%2,%3}, [%4];"
        : "=r"(r[0]), "=r"(r[1]), "=r"(r[2]), "=r"(r[3]) : "r"(addr));
}
__device__ __forceinline__ void cpasync16(uint32_t daddr, const void* g) {
    asm volatile("cp.async.cg.shared.global [%0], [%1], 16;" :: "r"(daddr), "l"(g) : "memory");
}
#define CP_COMMIT() asm volatile("cp.async.commit_group;" ::: "memory")
#define CP_WAIT0()  asm volatile("cp.async.wait_group 0;" ::: "memory")
#define CP_WAIT1()  asm volatile("cp.async.wait_group 1;" ::: "memory")

// ---------------------------------------------------------------------------
// Weight transpose to fp16: W[K][NC] f32 -> [NC][K] fp16
__global__ void tsplit_h(const float* __restrict__ W, __half* __restrict__ hi,
                         int K, int NC)
{
    __shared__ float tile[32][33];
    int k0 = blockIdx.y * 32, n0 = blockIdx.x * 32;
    int tx = threadIdx.x, ty = threadIdx.y;   // 32 x 8
    #pragma unroll
    for (int i = 0; i < 32; i += 8)
        tile[ty + i][tx] = W[(size_t)(k0 + ty + i) * NC + n0 + tx];
    __syncthreads();
    #pragma unroll
    for (int i = 0; i < 32; i += 8)
        hi[(size_t)(n0 + ty + i) * K + k0 + tx] = __float2half_rn(tile[tx][ty + i]);
}

// ---------------------------------------------------------------------------
// combine_split: out = (1+eps)*x + aggr, fp16 hi/lo
__global__ void combine_split(const float4* __restrict__ x, const float4* __restrict__ aggr,
                              const float* __restrict__ epsp,
                              uint2* __restrict__ hi, uint2* __restrict__ lo, int n4)
{
    float c1 = 1.0f + __ldg(epsp);
    int i = blockIdx.x * blockDim.x + threadIdx.x;
    int stride = gridDim.x * blockDim.x;
    for (; i < n4; i += stride) {
        float4 xv = x[i], av = aggr[i];
        float v0 = c1 * xv.x + av.x, v1 = c1 * xv.y + av.y;
        float v2 = c1 * xv.z + av.z, v3 = c1 * xv.w + av.w;
        uint2 hw, lw;
        split2h(v0, v1, hw.x, lw.x);
        split2h(v2, v3, hw.y, lw.y);
        hi[i] = hw; lo[i] = lw;
    }
}

// bnsilu_split: out = silu(in*scale[col]+shift[col]), fp16 hi/lo
__global__ void bnsilu_split(const float4* __restrict__ in, const float* __restrict__ bnp,
                             uint2* __restrict__ hi, uint2* __restrict__ lo,
                             int c4mask, int nc4, size_t n4)
{
    size_t i = (size_t)blockIdx.x * blockDim.x + threadIdx.x;
    size_t stride = (size_t)gridDim.x * blockDim.x;
    for (; i < n4; i += stride) {
        int c4 = (int)(i & (size_t)c4mask);
        float4 v  = in[i];
        float4 sc = reinterpret_cast<const float4*>(bnp)[c4];
        float4 sh = reinterpret_cast<const float4*>(bnp)[nc4 + c4];
        float y0 = v.x * sc.x + sh.x, y1 = v.y * sc.y + sh.y;
        float y2 = v.z * sc.z + sh.z, y3 = v.w * sc.w + sh.w;
        float s0 = y0 / (1.0f + __expf(-y0));
        float s1 = y1 / (1.0f + __expf(-y1));
        float s2 = y2 / (1.0f + __expf(-y2));
        float s3 = y3 / (1.0f + __expf(-y3));
        uint2 hw, lw;
        split2h(s0, s1, hw.x, lw.x);
        split2h(s2, s3, hw.y, lw.y);
        hi[i] = hw; lo[i] = lw;
    }
}

// ---------------------------------------------------------------------------
// Tensorized edge kernel: aggr[dst] += relu(x[src] + ea@We + be)
// FULL We^T resident in smem (one load, ONE syncthreads total) -> warps run
// all 4 column passes independently. Coalesced half-tile epilogue.
#define EP 36
#define EAH 0
#define EBW 4608
#define EIDX 23040
#define ESTG 23296
#define EDGE_SMEM_BYTES ((23296 + 8 * 16 * 36) * 4)   // 111616

__global__ void __launch_bounds__(256, 2) edge_mma(
    const float* __restrict__ x, const float* __restrict__ ea,
    const int* __restrict__ src, const int* __restrict__ dst,
    const __half* __restrict__ wet,
    const float* __restrict__ be, float* __restrict__ aggr, int E)
{
    extern __shared__ uint32_t sm[];
    uint32_t sb = smem_u32(sm);
    int t = threadIdx.x, warp = t >> 5, lane = t & 31;
    int wm = warp >> 1, wn = warp & 1;
    int g = lane >> 2, qt = lane & 3;
    int lr = lane & 7, lm1 = (lane >> 3) & 1, lm2 = lane >> 4;
    int e0 = blockIdx.x * 128;

    // Full B load: 512 rows x 8 chunks(16B) = 4096 cells = 16 per thread
    #pragma unroll
    for (int i = 0; i < 16; i++) {
        int cell = t + (i << 8);
        int n = cell >> 3, ch = cell & 7;
        cpasync16(sb + (EBW + n * EP + ch * 4) * 4, wet + (size_t)n * EDIM + ch * 8);
    }
    CP_COMMIT();

    // indices to smem
    if (t < 128) {
        int e = e0 + t;
        ((int*)sm)[EIDX + t] = (e < E) ? __ldg(&src[e]) : 0;
    } else {
        int e = e0 + (t - 128);
        ((int*)sm)[EIDX + t] = (e < E) ? __ldg(&dst[e]) : 0;
    }

    // ea tile load (single fp16): 128 rows x 64 f32
    #pragma unroll
    for (int i = 0; i < 8; i++) {
        int idx = t + (i << 8);
        int row = idx >> 4, f4 = idx & 15;
        int e = e0 + row;
        float4 v = make_float4(0.f, 0.f, 0.f, 0.f);
        if (e < E) v = __ldg(reinterpret_cast<const float4*>(ea + (size_t)e * EDIM + f4 * 4));
        int w = EAH + row * EP + f4 * 2;
        sm[w]     = pack2h(v.x, v.y);
        sm[w + 1] = pack2h(v.z, v.w);
    }

    CP_WAIT0();
    __syncthreads();   // the ONLY block-wide barrier

    int arow = wm * 32 + lr + 8 * lm1;
    int brow = wn * 64 + lr + 8 * lm2;
    float* stg = reinterpret_cast<float*>(sm + ESTG) + warp * (16 * 36);
    int r4 = lane >> 3, ch8 = lane & 7;   // epilogue: 4 rows x 8 float4-chunks

    #pragma unroll 1
    for (int pass = 0; pass < 4; pass++) {
        float acc[2][8][4];
        #pragma unroll
        for (int mf = 0; mf < 2; mf++)
            #pragma unroll
            for (int nf = 0; nf < 8; nf++)
                #pragma unroll
                for (int r = 0; r < 4; r++) acc[mf][nf][r] = 0.0f;

        #pragma unroll
        for (int ks = 0; ks < 4; ks++) {
            uint32_t af[2][4], bb[8][2];
            #pragma unroll
            for (int mf = 0; mf < 2; mf++)
                ldm_x4(af[mf], sb + (EAH + (arow + mf * 16) * EP + ks * 8 + 4 * lm2) * 4);
            #pragma unroll
            for (int np = 0; np < 4; np++) {
                uint32_t r[4];
                ldm_x4(r, sb + (EBW + (pass * 128 + brow + np * 16) * EP + ks * 8 + 4 * lm1) * 4);
                bb[np * 2][0] = r[0]; bb[np * 2][1] = r[1];
                bb[np * 2 + 1][0] = r[2]; bb[np * 2 + 1][1] = r[3];
            }
            #pragma unroll
            for (int mf = 0; mf < 2; mf++)
                #pragma unroll
                for (int nf = 0; nf < 8; nf++)
                    mma_f16(acc[mf][nf], af[mf], bb[nf]);
        }

        // epilogue: per mf (16 rows) x per col-half (32 cols), coalesced
        int colbase = pass * 128 + wn * 64;
        #pragma unroll
        for (int mf = 0; mf < 2; mf++) {
            #pragma unroll
            for (int hc = 0; hc < 2; hc++) {
                __syncwarp();
                #pragma unroll
                for (int nf2 = 0; nf2 < 4; nf2++) {
                    int nf = hc * 4 + nf2;
                    #pragma unroll
                    for (int h = 0; h < 2; h++) {
                        float2 o;
                        o.x = acc[mf][nf][2 * h];
                        o.y = acc[mf][nf][2 * h + 1];
                        *reinterpret_cast<float2*>(&stg[(g + 8 * h) * 36 + nf2 * 8 + 2 * qt]) = o;
                    }
                }
                __syncwarp();
                int cb = colbase + hc * 32;
                float4 bv = __ldg(reinterpret_cast<const float4*>(be + cb) + ch8);
                #pragma unroll
                for (int it = 0; it < 4; it++) {
                    int rloc = it * 4 + r4;
                    int loc = wm * 32 + mf * 16 + rloc;
                    int e = e0 + loc;
                    if (e < E) {
                        int s = ((int*)sm)[EIDX + loc];
                        int d = ((int*)sm)[EIDX + 128 + loc];
                        float4 m4 = *reinterpret_cast<const float4*>(stg + rloc * 36 + ch8 * 4);
                        float4 xv = __ldg(reinterpret_cast<const float4*>(x + (size_t)s * HID + cb) + ch8);
                        float r0 = fmaxf(m4.x + xv.x + bv.x, 0.f);
                        float r1 = fmaxf(m4.y + xv.y + bv.y, 0.f);
                        float r2 = fmaxf(m4.z + xv.z + bv.z, 0.f);
                        float r3 = fmaxf(m4.w + xv.w + bv.w, 0.f);
                        float* ar = aggr + (size_t)d * HID + cb + ch8 * 4;
                        asm volatile("red.global.add.v4.f32 [%0], {%1,%2,%3,%4};"
                                     :: "l"(ar), "f"(r0), "f"(r1), "f"(r2), "f"(r3) : "memory");
                    }
                }
            }
        }
    }
}

// ---------------------------------------------------------------------------
// Pure-DMA fp16 A-split (2x) HMMA GEMM, triple-buffered cp.async ring.
#define GP 20
#define GAH 0
#define GAL 2560
#define GBH 5120
#define GBUF 7680
#define GSTAT (3 * GBUF)
#define GEMM_SMEM_BYTES ((3 * GBUF + 256) * 4)   // 93184

__global__ void __launch_bounds__(256, 2) mma_gemm(
    const __half* __restrict__ Ah, const __half* __restrict__ Al,
    const __half* __restrict__ Bh, const float* __restrict__ bias,
    float* __restrict__ C, float* __restrict__ stats,
    int M, int K, int NC)
{
    extern __shared__ uint32_t sm[];
    uint32_t sb = smem_u32(sm);
    float* sSum = reinterpret_cast<float*>(sm + GSTAT);
    float* sSq  = sSum + 128;

    int t = threadIdx.x, warp = t >> 5, lane = t & 31;
    int wm = warp >> 1, wn = warp & 1;
    int g = lane >> 2, qt = lane & 3;
    int lr = lane & 7, lm1 = (lane >> 3) & 1, lm2 = lane >> 4;
    int bm = blockIdx.y * 128, bn = blockIdx.x * 128;
    int arow = wm * 32 + lr + 8 * lm1;
    int brow = wn * 64 + lr + 8 * lm2;

    float acc[2][8][4];
    #pragma unroll
    for (int mf = 0; mf < 2; mf++)
        #pragma unroll
        for (int nf = 0; nf < 8; nf++)
            #pragma unroll
            for (int r = 0; r < 4; r++) acc[mf][nf][r] = 0.0f;

    auto issue = [&](int kt, int buf) {
        uint32_t b0 = buf * GBUF;
        #pragma unroll
        for (int i = 0; i < 6; i++) {
            int cell = t + (i << 8);
            int reg = cell >> 9;
            int rem = cell & 511;
            int n = rem >> 2, ch = rem & 3;
            const __half* gp;
            uint32_t roff;
            if (reg == 0)      { gp = Ah + (size_t)(bm + n) * K + kt + ch * 8; roff = GAH; }
            else if (reg == 1) { gp = Al + (size_t)(bm + n) * K + kt + ch * 8; roff = GAL; }
            else               { gp = Bh + (size_t)(bn + n) * K + kt + ch * 8; roff = GBH; }
            cpasync16(sb + (b0 + roff + n * GP + ch * 4) * 4, gp);
        }
        CP_COMMIT();
    };

    int S = K / 32;
    issue(0, 0);
    issue(32, 1);

    for (int s = 0; s < S; s++) {
        if (s == S - 1) CP_WAIT0(); else CP_WAIT1();
        __syncthreads();
        if (s + 2 < S) issue((s + 2) * 32, (s + 2) % 3);
        uint32_t b0 = (uint32_t)((s % 3) * GBUF);
        #pragma unroll
        for (int ks = 0; ks < 2; ks++) {
            uint32_t af[2][4], al2[2][4], bb[8][2];
            #pragma unroll
            for (int mf = 0; mf < 2; mf++) {
                ldm_x4(af[mf],  sb + (b0 + GAH + (arow + mf * 16) * GP + ks * 8 + 4 * lm2) * 4);
                ldm_x4(al2[mf], sb + (b0 + GAL + (arow + mf * 16) * GP + ks * 8 + 4 * lm2) * 4);
            }
            #pragma unroll
            for (int np = 0; np < 4; np++) {
                uint32_t r[4];
                ldm_x4(r, sb + (b0 + GBH + (brow + np * 16) * GP + ks * 8 + 4 * lm1) * 4);
                bb[np * 2][0] = r[0]; bb[np * 2][1] = r[1];
                bb[np * 2 + 1][0] = r[2]; bb[np * 2 + 1][1] = r[3];
            }
            #pragma unroll
            for (int mf = 0; mf < 2; mf++)
                #pragma unroll
                for (int nf = 0; nf < 8; nf++)
                    mma_f16(acc[mf][nf], af[mf], bb[nf]);    // hi*b
            #pragma unroll
            for (int mf = 0; mf < 2; mf++)
                #pragma unroll
                for (int nf = 0; nf < 8; nf++)
                    mma_f16(acc[mf][nf], al2[mf], bb[nf]);   // lo*b
        }
    }

    // Epilogue: bias, store, column stats
    __syncthreads();
    if (t < 128) { sSum[t] = 0.0f; sSq[t] = 0.0f; }
    __syncthreads();

    float2 bv[8];
    #pragma unroll
    for (int nf = 0; nf < 8; nf++)
        bv[nf] = __ldg(reinterpret_cast<const float2*>(bias + bn + wn * 64 + nf * 8 + 2 * qt));

    float colsum[8][2], colsq[8][2];
    #pragma unroll
    for (int nf = 0; nf < 8; nf++) {
        colsum[nf][0] = 0.f; colsum[nf][1] = 0.f;
        colsq[nf][0] = 0.f;  colsq[nf][1] = 0.f;
    }

    #pragma unroll
    for (int mf = 0; mf < 2; mf++)
        #pragma unroll
        for (int half = 0; half < 2; half++) {
            int row = bm + wm * 32 + mf * 16 + g + 8 * half;
            if (row < M) {
                #pragma unroll
                for (int nf = 0; nf < 8; nf++) {
                    float v0 = acc[mf][nf][2 * half]     + bv[nf].x;
                    float v1 = acc[mf][nf][2 * half + 1] + bv[nf].y;
                    colsum[nf][0] += v0; colsq[nf][0] += v0 * v0;
                    colsum[nf][1] += v1; colsq[nf][1] += v1 * v1;
                    float2 o; o.x = v0; o.y = v1;
                    *reinterpret_cast<float2*>(C + (size_t)row * NC + bn + wn * 64 + nf * 8 + 2 * qt) = o;
                }
            }
        }
    #pragma unroll
    for (int nf = 0; nf < 8; nf++) {
        int cb = wn * 64 + nf * 8 + 2 * qt;
        atomicAdd(&sSum[cb],     colsum[nf][0]);
        atomicAdd(&sSum[cb + 1], colsum[nf][1]);
        atomicAdd(&sSq[cb],      colsq[nf][0]);
        atomicAdd(&sSq[cb + 1],  colsq[nf][1]);
    }
    __syncthreads();
    if (t < 128) {
        atomicAdd(&stats[bn + t],      sSum[t]);
        atomicAdd(&stats[NC + bn + t], sSq[t]);
    }
}

// ---------------------------------------------------------------------------
__global__ void bnfin_kernel(const float* __restrict__ stats,
                             const float* __restrict__ g, const float* __restrict__ beta,
                             float* __restrict__ bnp, int NC, float invN)
{
    int c = blockIdx.x * blockDim.x + threadIdx.x;
    if (c < NC) {
        float mu   = stats[c] * invN;
        float var  = stats[NC + c] * invN - mu * mu;
        float rstd = rsqrtf(var + BN_EPS);
        float sc   = g[c] * rstd;
        bnp[c]      = sc;
        bnp[NC + c] = beta[c] - mu * sc;
    }
}

__global__ void bnsilu_kernel(const float* __restrict__ in, float* __restrict__ out,
                              const float* __restrict__ bnp, int c4mask, int nc4, size_t n4)
{
    size_t i = (size_t)blockIdx.x * blockDim.x + threadIdx.x;
    size_t stride = (size_t)gridDim.x * blockDim.x;
    for (; i < n4; i += stride) {
        int c4 = (int)(i & (size_t)c4mask);
        float4 v  = reinterpret_cast<const float4*>(in)[i];
        float4 sc = reinterpret_cast<const float4*>(bnp)[c4];
        float4 sh = reinterpret_cast<const float4*>(bnp)[nc4 + c4];
        float y0 = v.x * sc.x + sh.x;
        float y1 = v.y * sc.y + sh.y;
        float y2 = v.z * sc.z + sh.z;
        float y3 = v.w * sc.w + sh.w;
        float4 r;
        r.x = y0 / (1.0f + __expf(-y0));
        r.y = y1 / (1.0f + __expf(-y1));
        r.z = y2 / (1.0f + __expf(-y2));
        r.w = y3 / (1.0f + __expf(-y3));
        reinterpret_cast<float4*>(out)[i] = r;
    }
}

// ---------------------------------------------------------------------------
extern "C" void kernel_launch(void* const* d_in, const int* in_sizes, int n_in,
                              void* d_out, int out_size)
{
    const float* x     = (const float*)d_in[0];
    const float* ea    = (const float*)d_in[1];
    const int*   ei    = (const int*)d_in[2];
    const float* We    = (const float*)d_in[3];
    const float* be    = (const float*)d_in[4];
    const float* W1    = (const float*)d_in[5];
    const float* b1    = (const float*)d_in[6];
    const float* g1    = (const float*)d_in[7];
    const float* beta1 = (const float*)d_in[8];
    const float* W2    = (const float*)d_in[9];
    const float* b2    = (const float*)d_in[10];
    const float* g2    = (const float*)d_in[11];
    const float* beta2 = (const float*)d_in[12];
    const float* epsp  = (const float*)d_in[13];

    int N = in_sizes[0] / HID;
    int E = in_sizes[1] / EDIM;
    const int* src = ei;
    const int* dst = ei + E;

    float *aggr, *h1, *h2, *stats1, *stats2, *bnp1, *bnp2;
    __half *w1t, *w2t, *wet, *cmbh, *cmbl, *h1sh, *h1sl;
    cudaGetSymbolAddress((void**)&aggr,   g_aggr);
    cudaGetSymbolAddress((void**)&h1,     g_h1);
    cudaGetSymbolAddress((void**)&h2,     g_h2);
    cudaGetSymbolAddress((void**)&stats1, g_stats1);
    cudaGetSymbolAddress((void**)&stats2, g_stats2);
    cudaGetSymbolAddress((void**)&bnp1,   g_bnp1);
    cudaGetSymbolAddress((void**)&bnp2,   g_bnp2);
    cudaGetSymbolAddress((void**)&w1t,    g_w1t);
    cudaGetSymbolAddress((void**)&w2t,    g_w2t);
    cudaGetSymbolAddress((void**)&wet,    g_wet);
    cudaGetSymbolAddress((void**)&cmbh,   g_cmb_hi);
    cudaGetSymbolAddress((void**)&cmbl,   g_cmb_lo);
    cudaGetSymbolAddress((void**)&h1sh,   g_h1s_hi);
    cudaGetSymbolAddress((void**)&h1sl,   g_h1s_lo);

    cudaFuncSetAttribute(edge_mma, cudaFuncAttributeMaxDynamicSharedMemorySize, EDGE_SMEM_BYTES);
    cudaFuncSetAttribute(mma_gemm, cudaFuncAttributeMaxDynamicSharedMemorySize, GEMM_SMEM_BYTES);

    // 0) zero aggr
    zero4_kernel<<<2048, 256>>>((float4*)aggr, N * HID / 4);
    // 1) split We
    tsplit_h<<<dim3(HID / 32, EDIM / 32), dim3(32, 8)>>>(We, wet, EDIM, HID);
    // 2) split W1 (filler so edge lands at profiled idx 3)
    tsplit_h<<<dim3(2 * HID / 32, HID / 32), dim3(32, 8)>>>(W1, w1t, HID, 2 * HID);
    // 3) tensorized edge message + scatter-add   <-- profiled
    edge_mma<<<(E + 127) / 128, 256, EDGE_SMEM_BYTES>>>(x, ea, src, dst, wet, be, aggr, E);
    // 4) combine + fp16 split
    combine_split<<<2048, 256>>>((const float4*)x, (const float4*)aggr, epsp,
                                 (uint2*)cmbh, (uint2*)cmbl, N * HID / 4);
    // 5) zero stats1
    zero_kernel<<<4, 256>>>(stats1, 4 * HID);
    // 6) GEMM1
    {
        dim3 grid((2 * HID) / 128, (N + 127) / 128);
        mma_gemm<<<grid, 256, GEMM_SMEM_BYTES>>>(cmbh, cmbl, w1t, b1, h1, stats1, N, HID, 2 * HID);
    }
    // 7) finalize BN1 params
    bnfin_kernel<<<(2 * HID + 255) / 256, 256>>>(stats1, g1, beta1, bnp1, 2 * HID, 1.0f / N);
    // 8) split W2
    tsplit_h<<<dim3(HID / 32, 2 * HID / 32), dim3(32, 8)>>>(W2, w2t, 2 * HID, HID);
    // 9) BN1+SiLU -> fp16 hi/lo
    bnsilu_split<<<2048, 256>>>((const float4*)h1, bnp1, (uint2*)h1sh, (uint2*)h1sl,
                                255, 256, (size_t)N * 2 * HID / 4);
    // 10) zero stats2
    zero_kernel<<<2, 256>>>(stats2, 2 * HID);
    // 11) GEMM2
    {
        dim3 grid(HID / 128, (N + 127) / 128);
        mma_gemm<<<grid, 256, GEMM_SMEM_BYTES>>>(h1sh, h1sl, w2t, b2, h2, stats2, N, 2 * HID, HID);
    }
    // 12) finalize BN2; 13) final BN + SiLU into d_out
    bnfin_kernel<<<(HID + 255) / 256, 256>>>(stats2, g2, beta2, bnp2, HID, 1.0f / N);
    bnsilu_kernel<<<2048, 256>>>(h2, (float*)d_out, bnp2, 127, 128, (size_t)N * HID / 4);
}

// round 15
// speedup vs baseline: 1.0136x; 1.0136x over previous
#include <cuda_runtime.h>
#include <cuda_fp16.h>
#include <cstdint>
#include <cstddef>

#define HID 512
#define EDIM 64
#define BN_EPS 1e-5f
#define MAXN 50000
#define MAXN2 50048
#define MAXE 400000

// ---------------------------------------------------------------------------
// Scratch (device globals; allocation in kernel_launch is forbidden)
__device__ float g_aggr[MAXN * HID];
__device__ float g_h1[MAXN2 * 2 * HID];
__device__ float g_h2[MAXN * HID];
__device__ float g_stats1[4 * HID];
__device__ float g_stats2[2 * HID];
__device__ float g_bnp1[4 * HID];
__device__ float g_bnp2[2 * HID];
__device__ __half g_w1t[2 * HID * HID];     // [1024][512] K-major fp16
__device__ __half g_w2t[HID * 2 * HID];     // [512][1024] K-major fp16
__device__ __half g_wet[HID * EDIM];        // [512][64]  K-major fp16
__device__ __half g_cmb_hi[MAXN2 * HID];    // GEMM1 A pre-split
__device__ __half g_cmb_lo[MAXN2 * HID];
__device__ __half g_h1s_hi[MAXN2 * 2 * HID];// GEMM2 A pre-split
__device__ __half g_h1s_lo[MAXN2 * 2 * HID];

// ---------------------------------------------------------------------------
__global__ void zero_kernel(float* __restrict__ p, int n) {
    int i = blockIdx.x * blockDim.x + threadIdx.x;
    int stride = gridDim.x * blockDim.x;
    for (; i < n; i += stride) p[i] = 0.0f;
}

// ---------------------------------------------------------------------------
__device__ __forceinline__ uint32_t smem_u32(const void* p) {
    uint32_t a;
    asm("{ .reg .u64 t; cvta.to.shared.u64 t, %1; cvt.u32.u64 %0, t; }" : "=r"(a) : "l"(p));
    return a;
}
__device__ __forceinline__ uint32_t pack2h(float a, float b) {
    return (uint32_t)__half_as_ushort(__float2half_rn(a))
         | ((uint32_t)__half_as_ushort(__float2half_rn(b)) << 16);
}
__device__ __forceinline__ void split2h(float a, float b, uint32_t& hw, uint32_t& lw) {
    __half ha = __float2half_rn(a), hb = __float2half_rn(b);
    float ra = a - __half2float(ha), rb = b - __half2float(hb);
    hw = (uint32_t)__half_as_ushort(ha) | ((uint32_t)__half_as_ushort(hb) << 16);
    lw = pack2h(ra, rb);
}
__device__ __forceinline__ void mma_f16(float c[4], const uint32_t a[4], const uint32_t b[2]) {
    asm volatile(
        "mma.sync.aligned.m16n8k16.row.col.f32.f16.f16.f32 "
        "{%0,%1,%2,%3}, {%4,%5,%6,%7}, {%8,%9}, {%0,%1,%2,%3};\n"
        : "+f"(c[0]), "+f"(c[1]), "+f"(c[2]), "+f"(c[3])
        : "r"(a[0]), "r"(a[1]), "r"(a[2]), "r"(a[3]), "r"(b[0]), "r"(b[1]));
}
__device__ __forceinline__ void ldm_x4(uint32_t r[4], uint32_t addr) {
    asm volatile("ldmatrix.sync.aligned.m8n8.x4.shared.b16 {%0,%1,%2,%3}, [%4];"
        : "=r"(r[0]), "=r"(r[1]), "=r"(r[2]), "=r"(r[3]) : "r"(addr));
}
__device__ __forceinline__ void cpasync16(uint32_t daddr, const void* g) {
    asm volatile("cp.async.cg.shared.global [%0], [%1], 16;" :: "r"(daddr), "l"(g) : "memory");
}
#define CP_COMMIT() asm volatile("cp.async.commit_group;" ::: "memory")
#define CP_WAIT0()  asm volatile("cp.async.wait_group 0;" ::: "memory")
#define CP_WAIT1()  asm volatile("cp.async.wait_group 1;" ::: "memory")

// ---------------------------------------------------------------------------
// prep_kernel: blockIdx-partitioned roles.
//  [0,32)      tsplit We  (grid 16x2)
//  [32,544)    tsplit W1  (grid 32x16)
//  [544,1056)  tsplit W2  (grid 16x32)
//  1056        zero stats1+stats2
//  [1057,...)  zero aggr (float4 grid-stride)
__device__ __forceinline__ void tsplit_tile(const float* __restrict__ W,
                                            __half* __restrict__ hi,
                                            int K, int NC, int bx, int by,
                                            float (*tile)[33])
{
    int k0 = by * 32, n0 = bx * 32;
    int tx = threadIdx.x, ty = threadIdx.y;   // 32 x 8
    #pragma unroll
    for (int i = 0; i < 32; i += 8)
        tile[ty + i][tx] = W[(size_t)(k0 + ty + i) * NC + n0 + tx];
    __syncthreads();
    #pragma unroll
    for (int i = 0; i < 32; i += 8)
        hi[(size_t)(n0 + ty + i) * K + k0 + tx] = __float2half_rn(tile[tx][ty + i]);
}

__global__ void prep_kernel(const float* __restrict__ We, const float* __restrict__ W1,
                            const float* __restrict__ W2,
                            __half* __restrict__ wet, __half* __restrict__ w1t,
                            __half* __restrict__ w2t,
                            float4* __restrict__ aggr, int n4,
                            float* __restrict__ stats1, float* __restrict__ stats2)
{
    __shared__ float tile[32][33];
    int b = blockIdx.x;
    int t = threadIdx.y * 32 + threadIdx.x;
    if (b < 32)        { tsplit_tile(We, wet, EDIM, HID, b & 15, b >> 4, tile); return; }
    b -= 32;
    if (b < 512)       { tsplit_tile(W1, w1t, HID, 2 * HID, b & 31, b >> 5, tile); return; }
    b -= 512;
    if (b < 512)       { tsplit_tile(W2, w2t, 2 * HID, HID, b & 15, b >> 4, tile); return; }
    b -= 512;
    if (b == 0) {
        for (int i = t; i < 4 * HID; i += 256) stats1[i] = 0.0f;
        for (int i = t; i < 2 * HID; i += 256) stats2[i] = 0.0f;
        return;
    }
    b -= 1;
    int nb = gridDim.x - 1057;
    float4 z = make_float4(0.f, 0.f, 0.f, 0.f);
    for (int i = b * 256 + t; i < n4; i += nb * 256) aggr[i] = z;
}

// ---------------------------------------------------------------------------
// combine_split: out = (1+eps)*x + aggr, fp16 hi/lo
__global__ void combine_split(const float4* __restrict__ x, const float4* __restrict__ aggr,
                              const float* __restrict__ epsp,
                              uint2* __restrict__ hi, uint2* __restrict__ lo, int n4)
{
    float c1 = 1.0f + __ldg(epsp);
    int i = blockIdx.x * blockDim.x + threadIdx.x;
    int stride = gridDim.x * blockDim.x;
    for (; i < n4; i += stride) {
        float4 xv = x[i], av = aggr[i];
        float v0 = c1 * xv.x + av.x, v1 = c1 * xv.y + av.y;
        float v2 = c1 * xv.z + av.z, v3 = c1 * xv.w + av.w;
        uint2 hw, lw;
        split2h(v0, v1, hw.x, lw.x);
        split2h(v2, v3, hw.y, lw.y);
        hi[i] = hw; lo[i] = lw;
    }
}

// bnsilu_split: out = silu(in*scale[col]+shift[col]), fp16 hi/lo
__global__ void bnsilu_split(const float4* __restrict__ in, const float* __restrict__ bnp,
                             uint2* __restrict__ hi, uint2* __restrict__ lo,
                             int c4mask, int nc4, size_t n4)
{
    size_t i = (size_t)blockIdx.x * blockDim.x + threadIdx.x;
    size_t stride = (size_t)gridDim.x * blockDim.x;
    for (; i < n4; i += stride) {
        int c4 = (int)(i & (size_t)c4mask);
        float4 v  = in[i];
        float4 sc = reinterpret_cast<const float4*>(bnp)[c4];
        float4 sh = reinterpret_cast<const float4*>(bnp)[nc4 + c4];
        float y0 = v.x * sc.x + sh.x, y1 = v.y * sc.y + sh.y;
        float y2 = v.z * sc.z + sh.z, y3 = v.w * sc.w + sh.w;
        float s0 = y0 / (1.0f + __expf(-y0));
        float s1 = y1 / (1.0f + __expf(-y1));
        float s2 = y2 / (1.0f + __expf(-y2));
        float s3 = y3 / (1.0f + __expf(-y3));
        uint2 hw, lw;
        split2h(s0, s1, hw.x, lw.x);
        split2h(s2, s3, hw.y, lw.y);
        hi[i] = hw; lo[i] = lw;
    }
}

// ---------------------------------------------------------------------------
// Tensorized edge kernel (R13 version): aggr[dst] += relu(x[src] + ea@We + be)
// Single fp16 A, double-buffered B prefetch, coalesced 2x16 epilogue.
#define EP 36
#define EAH 0
#define EB0 4608
#define EB1 9216
#define EIDX 13824
#define ESTG 14080
#define EDGE_SMEM_BYTES ((14080 + 8 * 16 * 68) * 4)   // 91136

__global__ void __launch_bounds__(256, 2) edge_mma(
    const float* __restrict__ x, const float* __restrict__ ea,
    const int* __restrict__ src, const int* __restrict__ dst,
    const __half* __restrict__ wet,
    const float* __restrict__ be, float* __restrict__ aggr, int E)
{
    extern __shared__ uint32_t sm[];
    uint32_t sb = smem_u32(sm);
    int t = threadIdx.x, warp = t >> 5, lane = t & 31;
    int wm = warp >> 1, wn = warp & 1;
    int g = lane >> 2, qt = lane & 3;
    int lr = lane & 7, lm1 = (lane >> 3) & 1, lm2 = lane >> 4;
    int e0 = blockIdx.x * 128;

    auto issueB = [&](int pass) {
        uint32_t off = (pass & 1) ? EB1 : EB0;
        #pragma unroll
        for (int i = 0; i < 4; i++) {
            int cell = t + (i << 8);
            int n = cell >> 3, ch = cell & 7;
            const __half* gp = wet + (size_t)(pass * 128 + n) * EDIM + ch * 8;
            cpasync16(sb + (off + n * EP + ch * 4) * 4, gp);
        }
        CP_COMMIT();
    };

    issueB(0);

    if (t < 128) {
        int e = e0 + t;
        ((int*)sm)[EIDX + t] = (e < E) ? __ldg(&src[e]) : 0;
    } else {
        int e = e0 + (t - 128);
        ((int*)sm)[EIDX + t] = (e < E) ? __ldg(&dst[e]) : 0;
    }

    // ea tile load (single fp16): 128 rows x 64 f32
    #pragma unroll
    for (int i = 0; i < 8; i++) {
        int idx = t + (i << 8);
        int row = idx >> 4, f4 = idx & 15;
        int e = e0 + row;
        float4 v = make_float4(0.f, 0.f, 0.f, 0.f);
        if (e < E) v = __ldg(reinterpret_cast<const float4*>(ea + (size_t)e * EDIM + f4 * 4));
        int w = EAH + row * EP + f4 * 2;
        sm[w]     = pack2h(v.x, v.y);
        sm[w + 1] = pack2h(v.z, v.w);
    }

    int arow = wm * 32 + lr + 8 * lm1;
    int brow = wn * 64 + lr + 8 * lm2;
    float* stg = reinterpret_cast<float*>(sm + ESTG) + warp * (16 * 68);
    int r2 = lane >> 4, ch16 = lane & 15;   // epilogue lane map: 2 rows x 16 col-chunks

    #pragma unroll 1
    for (int pass = 0; pass < 4; pass++) {
        if (pass == 3) CP_WAIT0(); else CP_WAIT1();
        __syncthreads();
        if (pass + 1 < 4) issueB(pass + 1);
        uint32_t eb = (pass & 1) ? EB1 : EB0;

        float acc[2][8][4];
        #pragma unroll
        for (int mf = 0; mf < 2; mf++)
            #pragma unroll
            for (int nf = 0; nf < 8; nf++)
                #pragma unroll
                for (int r = 0; r < 4; r++) acc[mf][nf][r] = 0.0f;

        #pragma unroll
        for (int ks = 0; ks < 4; ks++) {
            uint32_t af[2][4], bb[8][2];
            #pragma unroll
            for (int mf = 0; mf < 2; mf++)
                ldm_x4(af[mf], sb + (EAH + (arow + mf * 16) * EP + ks * 8 + 4 * lm2) * 4);
            #pragma unroll
            for (int np = 0; np < 4; np++) {
                uint32_t r[4];
                ldm_x4(r, sb + (eb + (brow + np * 16) * EP + ks * 8 + 4 * lm1) * 4);
                bb[np * 2][0] = r[0]; bb[np * 2][1] = r[1];
                bb[np * 2 + 1][0] = r[2]; bb[np * 2 + 1][1] = r[3];
            }
            #pragma unroll
            for (int mf = 0; mf < 2; mf++)
                #pragma unroll
                for (int nf = 0; nf < 8; nf++)
                    mma_f16(acc[mf][nf], af[mf], bb[nf]);
        }

        // epilogue: stage -> coalesced gather x -> relu -> RED.v4
        int cg2 = pass * 128 + wn * 64;
        float4 bv4 = __ldg(reinterpret_cast<const float4*>(be + cg2) + ch16);

        #pragma unroll
        for (int mf = 0; mf < 2; mf++) {
            __syncwarp();
            #pragma unroll
            for (int nf = 0; nf < 8; nf++)
                #pragma unroll
                for (int h = 0; h < 2; h++) {
                    float2 o;
                    o.x = acc[mf][nf][2 * h];
                    o.y = acc[mf][nf][2 * h + 1];
                    *reinterpret_cast<float2*>(&stg[(g + 8 * h) * 68 + nf * 8 + 2 * qt]) = o;
                }
            __syncwarp();
            #pragma unroll
            for (int it = 0; it < 8; it++) {
                int rloc = it * 2 + r2;
                int loc = wm * 32 + mf * 16 + rloc;
                int e = e0 + loc;
                if (e < E) {
                    int s = ((int*)sm)[EIDX + loc];
                    int d = ((int*)sm)[EIDX + 128 + loc];
                    float4 m4 = *reinterpret_cast<const float4*>(stg + rloc * 68 + ch16 * 4);
                    float4 xv = __ldg(reinterpret_cast<const float4*>(x + (size_t)s * HID + cg2) + ch16);
                    float r0 = fmaxf(m4.x + xv.x + bv4.x, 0.f);
                    float r1 = fmaxf(m4.y + xv.y + bv4.y, 0.f);
                    float r2f = fmaxf(m4.z + xv.z + bv4.z, 0.f);
                    float r3 = fmaxf(m4.w + xv.w + bv4.w, 0.f);
                    float* ar = aggr + (size_t)d * HID + cg2 + ch16 * 4;
                    asm volatile("red.global.add.v4.f32 [%0], {%1,%2,%3,%4};"
                                 :: "l"(ar), "f"(r0), "f"(r1), "f"(r2f), "f"(r3) : "memory");
                }
            }
        }
    }
}

// ---------------------------------------------------------------------------
// Pure-DMA fp16 A-split (2x) HMMA GEMM, triple-buffered cp.async ring.
#define GP 20
#define GAH 0
#define GAL 2560
#define GBH 5120
#define GBUF 7680
#define GSTAT (3 * GBUF)
#define GEMM_SMEM_BYTES ((3 * GBUF + 256) * 4)   // 93184

__global__ void __launch_bounds__(256, 2) mma_gemm(
    const __half* __restrict__ Ah, const __half* __restrict__ Al,
    const __half* __restrict__ Bh, const float* __restrict__ bias,
    float* __restrict__ C, float* __restrict__ stats,
    int M, int K, int NC)
{
    extern __shared__ uint32_t sm[];
    uint32_t sb = smem_u32(sm);
    float* sSum = reinterpret_cast<float*>(sm + GSTAT);
    float* sSq  = sSum + 128;

    int t = threadIdx.x, warp = t >> 5, lane = t & 31;
    int wm = warp >> 1, wn = warp & 1;
    int g = lane >> 2, qt = lane & 3;
    int lr = lane & 7, lm1 = (lane >> 3) & 1, lm2 = lane >> 4;
    int bm = blockIdx.y * 128, bn = blockIdx.x * 128;
    int arow = wm * 32 + lr + 8 * lm1;
    int brow = wn * 64 + lr + 8 * lm2;

    float acc[2][8][4];
    #pragma unroll
    for (int mf = 0; mf < 2; mf++)
        #pragma unroll
        for (int nf = 0; nf < 8; nf++)
            #pragma unroll
            for (int r = 0; r < 4; r++) acc[mf][nf][r] = 0.0f;

    auto issue = [&](int kt, int buf) {
        uint32_t b0 = buf * GBUF;
        #pragma unroll
        for (int i = 0; i < 6; i++) {
            int cell = t + (i << 8);
            int reg = cell >> 9;
            int rem = cell & 511;
            int n = rem >> 2, ch = rem & 3;
            const __half* gp;
            uint32_t roff;
            if (reg == 0)      { gp = Ah + (size_t)(bm + n) * K + kt + ch * 8; roff = GAH; }
            else if (reg == 1) { gp = Al + (size_t)(bm + n) * K + kt + ch * 8; roff = GAL; }
            else               { gp = Bh + (size_t)(bn + n) * K + kt + ch * 8; roff = GBH; }
            cpasync16(sb + (b0 + roff + n * GP + ch * 4) * 4, gp);
        }
        CP_COMMIT();
    };

    int S = K / 32;
    issue(0, 0);
    issue(32, 1);

    for (int s = 0; s < S; s++) {
        if (s == S - 1) CP_WAIT0(); else CP_WAIT1();
        __syncthreads();
        if (s + 2 < S) issue((s + 2) * 32, (s + 2) % 3);
        uint32_t b0 = (uint32_t)((s % 3) * GBUF);
        #pragma unroll
        for (int ks = 0; ks < 2; ks++) {
            uint32_t af[2][4], al2[2][4], bb[8][2];
            #pragma unroll
            for (int mf = 0; mf < 2; mf++) {
                ldm_x4(af[mf],  sb + (b0 + GAH + (arow + mf * 16) * GP + ks * 8 + 4 * lm2) * 4);
                ldm_x4(al2[mf], sb + (b0 + GAL + (arow + mf * 16) * GP + ks * 8 + 4 * lm2) * 4);
            }
            #pragma unroll
            for (int np = 0; np < 4; np++) {
                uint32_t r[4];
                ldm_x4(r, sb + (b0 + GBH + (brow + np * 16) * GP + ks * 8 + 4 * lm1) * 4);
                bb[np * 2][0] = r[0]; bb[np * 2][1] = r[1];
                bb[np * 2 + 1][0] = r[2]; bb[np * 2 + 1][1] = r[3];
            }
            #pragma unroll
            for (int mf = 0; mf < 2; mf++)
                #pragma unroll
                for (int nf = 0; nf < 8; nf++)
                    mma_f16(acc[mf][nf], af[mf], bb[nf]);    // hi*b
            #pragma unroll
            for (int mf = 0; mf < 2; mf++)
                #pragma unroll
                for (int nf = 0; nf < 8; nf++)
                    mma_f16(acc[mf][nf], al2[mf], bb[nf]);   // lo*b
        }
    }

    // Epilogue: bias, store, column stats
    __syncthreads();
    if (t < 128) { sSum[t] = 0.0f; sSq[t] = 0.0f; }
    __syncthreads();

    float2 bv[8];
    #pragma unroll
    for (int nf = 0; nf < 8; nf++)
        bv[nf] = __ldg(reinterpret_cast<const float2*>(bias + bn + wn * 64 + nf * 8 + 2 * qt));

    float colsum[8][2], colsq[8][2];
    #pragma unroll
    for (int nf = 0; nf < 8; nf++) {
        colsum[nf][0] = 0.f; colsum[nf][1] = 0.f;
        colsq[nf][0] = 0.f;  colsq[nf][1] = 0.f;
    }

    #pragma unroll
    for (int mf = 0; mf < 2; mf++)
        #pragma unroll
        for (int half = 0; half < 2; half++) {
            int row = bm + wm * 32 + mf * 16 + g + 8 * half;
            if (row < M) {
                #pragma unroll
                for (int nf = 0; nf < 8; nf++) {
                    float v0 = acc[mf][nf][2 * half]     + bv[nf].x;
                    float v1 = acc[mf][nf][2 * half + 1] + bv[nf].y;
                    colsum[nf][0] += v0; colsq[nf][0] += v0 * v0;
                    colsum[nf][1] += v1; colsq[nf][1] += v1 * v1;
                    float2 o; o.x = v0; o.y = v1;
                    *reinterpret_cast<float2*>(C + (size_t)row * NC + bn + wn * 64 + nf * 8 + 2 * qt) = o;
                }
            }
        }
    #pragma unroll
    for (int nf = 0; nf < 8; nf++) {
        int cb = wn * 64 + nf * 8 + 2 * qt;
        atomicAdd(&sSum[cb],     colsum[nf][0]);
        atomicAdd(&sSum[cb + 1], colsum[nf][1]);
        atomicAdd(&sSq[cb],      colsq[nf][0]);
        atomicAdd(&sSq[cb + 1],  colsq[nf][1]);
    }
    __syncthreads();
    if (t < 128) {
        atomicAdd(&stats[bn + t],      sSum[t]);
        atomicAdd(&stats[NC + bn + t], sSq[t]);
    }
}

// ---------------------------------------------------------------------------
__global__ void bnfin_kernel(const float* __restrict__ stats,
                             const float* __restrict__ g, const float* __restrict__ beta,
                             float* __restrict__ bnp, int NC, float invN)
{
    int c = blockIdx.x * blockDim.x + threadIdx.x;
    if (c < NC) {
        float mu   = stats[c] * invN;
        float var  = stats[NC + c] * invN - mu * mu;
        float rstd = rsqrtf(var + BN_EPS);
        float sc   = g[c] * rstd;
        bnp[c]      = sc;
        bnp[NC + c] = beta[c] - mu * sc;
    }
}

__global__ void bnsilu_kernel(const float* __restrict__ in, float* __restrict__ out,
                              const float* __restrict__ bnp, int c4mask, int nc4, size_t n4)
{
    size_t i = (size_t)blockIdx.x * blockDim.x + threadIdx.x;
    size_t stride = (size_t)gridDim.x * blockDim.x;
    for (; i < n4; i += stride) {
        int c4 = (int)(i & (size_t)c4mask);
        float4 v  = reinterpret_cast<const float4*>(in)[i];
        float4 sc = reinterpret_cast<const float4*>(bnp)[c4];
        float4 sh = reinterpret_cast<const float4*>(bnp)[nc4 + c4];
        float y0 = v.x * sc.x + sh.x;
        float y1 = v.y * sc.y + sh.y;
        float y2 = v.z * sc.z + sh.z;
        float y3 = v.w * sc.w + sh.w;
        float4 r;
        r.x = y0 / (1.0f + __expf(-y0));
        r.y = y1 / (1.0f + __expf(-y1));
        r.z = y2 / (1.0f + __expf(-y2));
        r.w = y3 / (1.0f + __expf(-y3));
        reinterpret_cast<float4*>(out)[i] = r;
    }
}

// ---------------------------------------------------------------------------
extern "C" void kernel_launch(void* const* d_in, const int* in_sizes, int n_in,
                              void* d_out, int out_size)
{
    const float* x     = (const float*)d_in[0];
    const float* ea    = (const float*)d_in[1];
    const int*   ei    = (const int*)d_in[2];
    const float* We    = (const float*)d_in[3];
    const float* be    = (const float*)d_in[4];
    const float* W1    = (const float*)d_in[5];
    const float* b1    = (const float*)d_in[6];
    const float* g1    = (const float*)d_in[7];
    const float* beta1 = (const float*)d_in[8];
    const float* W2    = (const float*)d_in[9];
    const float* b2    = (const float*)d_in[10];
    const float* g2    = (const float*)d_in[11];
    const float* beta2 = (const float*)d_in[12];
    const float* epsp  = (const float*)d_in[13];

    int N = in_sizes[0] / HID;
    int E = in_sizes[1] / EDIM;
    const int* src = ei;
    const int* dst = ei + E;

    float *aggr, *h1, *h2, *stats1, *stats2, *bnp1, *bnp2;
    __half *w1t, *w2t, *wet, *cmbh, *cmbl, *h1sh, *h1sl;
    cudaGetSymbolAddress((void**)&aggr,   g_aggr);
    cudaGetSymbolAddress((void**)&h1,     g_h1);
    cudaGetSymbolAddress((void**)&h2,     g_h2);
    cudaGetSymbolAddress((void**)&stats1, g_stats1);
    cudaGetSymbolAddress((void**)&stats2, g_stats2);
    cudaGetSymbolAddress((void**)&bnp1,   g_bnp1);
    cudaGetSymbolAddress((void**)&bnp2,   g_bnp2);
    cudaGetSymbolAddress((void**)&w1t,    g_w1t);
    cudaGetSymbolAddress((void**)&w2t,    g_w2t);
    cudaGetSymbolAddress((void**)&wet,    g_wet);
    cudaGetSymbolAddress((void**)&cmbh,   g_cmb_hi);
    cudaGetSymbolAddress((void**)&cmbl,   g_cmb_lo);
    cudaGetSymbolAddress((void**)&h1sh,   g_h1s_hi);
    cudaGetSymbolAddress((void**)&h1sl,   g_h1s_lo);

    cudaFuncSetAttribute(edge_mma, cudaFuncAttributeMaxDynamicSharedMemorySize, EDGE_SMEM_BYTES);
    cudaFuncSetAttribute(mma_gemm, cudaFuncAttributeMaxDynamicSharedMemorySize, GEMM_SMEM_BYTES);

    // 0) prep: zero aggr/stats + all weight transposes (one kernel)
    prep_kernel<<<2081, dim3(32, 8)>>>(We, W1, W2, wet, w1t, w2t,
                                       (float4*)aggr, N * HID / 4, stats1, stats2);
    // 1) tensorized edge message + scatter-add
    edge_mma<<<(E + 127) / 128, 256, EDGE_SMEM_BYTES>>>(x, ea, src, dst, wet, be, aggr, E);
    // 2) combine + fp16 split
    combine_split<<<2048, 256>>>((const float4*)x, (const float4*)aggr, epsp,
                                 (uint2*)cmbh, (uint2*)cmbl, N * HID / 4);
    // 3) GEMM1   <-- profiled slot
    {
        dim3 grid((2 * HID) / 128, (N + 127) / 128);
        mma_gemm<<<grid, 256, GEMM_SMEM_BYTES>>>(cmbh, cmbl, w1t, b1, h1, stats1, N, HID, 2 * HID);
    }
    // 4) finalize BN1 params
    bnfin_kernel<<<(2 * HID + 255) / 256, 256>>>(stats1, g1, beta1, bnp1, 2 * HID, 1.0f / N);
    // 5) BN1+SiLU -> fp16 hi/lo
    bnsilu_split<<<2048, 256>>>((const float4*)h1, bnp1, (uint2*)h1sh, (uint2*)h1sl,
                                255, 256, (size_t)N * 2 * HID / 4);
    // 6) GEMM2
    {
        dim3 grid(HID / 128, (N + 127) / 128);
        mma_gemm<<<grid, 256, GEMM_SMEM_BYTES>>>(h1sh, h1sl, w2t, b2, h2, stats2, N, 2 * HID, HID);
    }
    // 7) finalize BN2; 8) final BN + SiLU into d_out
    bnfin_kernel<<<(HID + 255) / 256, 256>>>(stats2, g2, beta2, bnp2, HID, 1.0f / N);
    bnsilu_kernel<<<2048, 256>>>(h2, (float*)d_out, bnp2, 127, 128, (size_t)N * HID / 4);
}

// round 16
// speedup vs baseline: 1.0235x; 1.0097x over previous
#include <cuda_runtime.h>
#include <cuda_fp16.h>
#include <cstdint>
#include <cstddef>

#define HID 512
#define EDIM 64
#define BN_EPS 1e-5f
#define MAXN 50000
#define MAXN2 50048
#define MAXE 400000

// ---------------------------------------------------------------------------
// Scratch (device globals; allocation in kernel_launch is forbidden)
__device__ float g_aggr[MAXN * HID];
__device__ float g_h1[MAXN2 * 2 * HID];
__device__ float g_h2[MAXN * HID];
__device__ float g_stats1[4 * HID];
__device__ float g_stats2[2 * HID];
__device__ float g_bnp1[4 * HID];
__device__ float g_bnp2[2 * HID];
__device__ __half g_w1t[2 * HID * HID];     // [1024][512] K-major fp16
__device__ __half g_w2t[HID * 2 * HID];     // [512][1024] K-major fp16
__device__ __half g_wet[HID * EDIM];        // [512][64]  K-major fp16
__device__ __half g_cmb_hi[MAXN2 * HID];    // GEMM1 A pre-split
__device__ __half g_cmb_lo[MAXN2 * HID];
__device__ __half g_h1s_hi[MAXN2 * 2 * HID];// GEMM2 A pre-split
__device__ __half g_h1s_lo[MAXN2 * 2 * HID];

// ---------------------------------------------------------------------------
__global__ void zero_kernel(float* __restrict__ p, int n) {
    int i = blockIdx.x * blockDim.x + threadIdx.x;
    int stride = gridDim.x * blockDim.x;
    for (; i < n; i += stride) p[i] = 0.0f;
}

// ---------------------------------------------------------------------------
__device__ __forceinline__ uint32_t smem_u32(const void* p) {
    uint32_t a;
    asm("{ .reg .u64 t; cvta.to.shared.u64 t, %1; cvt.u32.u64 %0, t; }" : "=r"(a) : "l"(p));
    return a;
}
__device__ __forceinline__ uint32_t pack2h(float a, float b) {
    return (uint32_t)__half_as_ushort(__float2half_rn(a))
         | ((uint32_t)__half_as_ushort(__float2half_rn(b)) << 16);
}
__device__ __forceinline__ void split2h(float a, float b, uint32_t& hw, uint32_t& lw) {
    __half ha = __float2half_rn(a), hb = __float2half_rn(b);
    float ra = a - __half2float(ha), rb = b - __half2float(hb);
    hw = (uint32_t)__half_as_ushort(ha) | ((uint32_t)__half_as_ushort(hb) << 16);
    lw = pack2h(ra, rb);
}
__device__ __forceinline__ void mma_f16(float c[4], const uint32_t a[4], const uint32_t b[2]) {
    asm volatile(
        "mma.sync.aligned.m16n8k16.row.col.f32.f16.f16.f32 "
        "{%0,%1,%2,%3}, {%4,%5,%6,%7}, {%8,%9}, {%0,%1,%2,%3};\n"
        : "+f"(c[0]), "+f"(c[1]), "+f"(c[2]), "+f"(c[3])
        : "r"(a[0]), "r"(a[1]), "r"(a[2]), "r"(a[3]), "r"(b[0]), "r"(b[1]));
}
__device__ __forceinline__ void ldm_x4(uint32_t r[4], uint32_t addr) {
    asm volatile("ldmatrix.sync.aligned.m8n8.x4.shared.b16 {%0,%1,%2,%3}, [%4];"
        : "=r"(r[0]), "=r"(r[1]), "=r"(r[2]), "=r"(r[3]) : "r"(addr));
}
__device__ __forceinline__ void cpasync16(uint32_t daddr, const void* g) {
    asm volatile("cp.async.cg.shared.global [%0], [%1], 16;" :: "r"(daddr), "l"(g) : "memory");
}
#define CP_COMMIT() asm volatile("cp.async.commit_group;" ::: "memory")
#define CP_WAIT0()  asm volatile("cp.async.wait_group 0;" ::: "memory")
#define CP_WAIT1()  asm volatile("cp.async.wait_group 1;" ::: "memory")

// ---------------------------------------------------------------------------
// prep_kernel: blockIdx-partitioned roles.
//  [0,32)      tsplit We  (grid 16x2)
//  [32,544)    tsplit W1  (grid 32x16)
//  [544,1056)  tsplit W2  (grid 16x32)
//  1056        zero stats1+stats2
//  [1057,...)  zero aggr (float4 grid-stride)
__device__ __forceinline__ void tsplit_tile(const float* __restrict__ W,
                                            __half* __restrict__ hi,
                                            int K, int NC, int bx, int by,
                                            float (*tile)[33])
{
    int k0 = by * 32, n0 = bx * 32;
    int tx = threadIdx.x, ty = threadIdx.y;   // 32 x 8
    #pragma unroll
    for (int i = 0; i < 32; i += 8)
        tile[ty + i][tx] = W[(size_t)(k0 + ty + i) * NC + n0 + tx];
    __syncthreads();
    #pragma unroll
    for (int i = 0; i < 32; i += 8)
        hi[(size_t)(n0 + ty + i) * K + k0 + tx] = __float2half_rn(tile[tx][ty + i]);
}

__global__ void prep_kernel(const float* __restrict__ We, const float* __restrict__ W1,
                            const float* __restrict__ W2,
                            __half* __restrict__ wet, __half* __restrict__ w1t,
                            __half* __restrict__ w2t,
                            float4* __restrict__ aggr, int n4,
                            float* __restrict__ stats1, float* __restrict__ stats2)
{
    __shared__ float tile[32][33];
    int b = blockIdx.x;
    int t = threadIdx.y * 32 + threadIdx.x;
    if (b < 32)        { tsplit_tile(We, wet, EDIM, HID, b & 15, b >> 4, tile); return; }
    b -= 32;
    if (b < 512)       { tsplit_tile(W1, w1t, HID, 2 * HID, b & 31, b >> 5, tile); return; }
    b -= 512;
    if (b < 512)       { tsplit_tile(W2, w2t, 2 * HID, HID, b & 15, b >> 4, tile); return; }
    b -= 512;
    if (b == 0) {
        for (int i = t; i < 4 * HID; i += 256) stats1[i] = 0.0f;
        for (int i = t; i < 2 * HID; i += 256) stats2[i] = 0.0f;
        return;
    }
    b -= 1;
    int nb = gridDim.x - 1057;
    float4 z = make_float4(0.f, 0.f, 0.f, 0.f);
    for (int i = b * 256 + t; i < n4; i += nb * 256) aggr[i] = z;
}

// ---------------------------------------------------------------------------
// combine_split: out = (1+eps)*x + aggr, fp16 hi/lo
__global__ void combine_split(const float4* __restrict__ x, const float4* __restrict__ aggr,
                              const float* __restrict__ epsp,
                              uint2* __restrict__ hi, uint2* __restrict__ lo, int n4)
{
    float c1 = 1.0f + __ldg(epsp);
    int i = blockIdx.x * blockDim.x + threadIdx.x;
    int stride = gridDim.x * blockDim.x;
    for (; i < n4; i += stride) {
        float4 xv = x[i], av = aggr[i];
        float v0 = c1 * xv.x + av.x, v1 = c1 * xv.y + av.y;
        float v2 = c1 * xv.z + av.z, v3 = c1 * xv.w + av.w;
        uint2 hw, lw;
        split2h(v0, v1, hw.x, lw.x);
        split2h(v2, v3, hw.y, lw.y);
        hi[i] = hw; lo[i] = lw;
    }
}

// bnsilu_split: out = silu(in*scale[col]+shift[col]), fp16 hi/lo
__global__ void bnsilu_split(const float4* __restrict__ in, const float* __restrict__ bnp,
                             uint2* __restrict__ hi, uint2* __restrict__ lo,
                             int c4mask, int nc4, size_t n4)
{
    size_t i = (size_t)blockIdx.x * blockDim.x + threadIdx.x;
    size_t stride = (size_t)gridDim.x * blockDim.x;
    for (; i < n4; i += stride) {
        int c4 = (int)(i & (size_t)c4mask);
        float4 v  = in[i];
        float4 sc = reinterpret_cast<const float4*>(bnp)[c4];
        float4 sh = reinterpret_cast<const float4*>(bnp)[nc4 + c4];
        float y0 = v.x * sc.x + sh.x, y1 = v.y * sc.y + sh.y;
        float y2 = v.z * sc.z + sh.z, y3 = v.w * sc.w + sh.w;
        float s0 = y0 / (1.0f + __expf(-y0));
        float s1 = y1 / (1.0f + __expf(-y1));
        float s2 = y2 / (1.0f + __expf(-y2));
        float s3 = y3 / (1.0f + __expf(-y3));
        uint2 hw, lw;
        split2h(s0, s1, hw.x, lw.x);
        split2h(s2, s3, hw.y, lw.y);
        hi[i] = hw; lo[i] = lw;
    }
}

// ---------------------------------------------------------------------------
// Tensorized edge kernel (R13 version): aggr[dst] += relu(x[src] + ea@We + be)
// Single fp16 A, double-buffered B prefetch, coalesced 2x16 epilogue.
#define EP 36
#define EAH 0
#define EB0 4608
#define EB1 9216
#define EIDX 13824
#define ESTG 14080
#define EDGE_SMEM_BYTES ((14080 + 8 * 16 * 68) * 4)   // 91136

__global__ void __launch_bounds__(256, 2) edge_mma(
    const float* __restrict__ x, const float* __restrict__ ea,
    const int* __restrict__ src, const int* __restrict__ dst,
    const __half* __restrict__ wet,
    const float* __restrict__ be, float* __restrict__ aggr, int E)
{
    extern __shared__ uint32_t sm[];
    uint32_t sb = smem_u32(sm);
    int t = threadIdx.x, warp = t >> 5, lane = t & 31;
    int wm = warp >> 1, wn = warp & 1;
    int g = lane >> 2, qt = lane & 3;
    int lr = lane & 7, lm1 = (lane >> 3) & 1, lm2 = lane >> 4;
    int e0 = blockIdx.x * 128;

    auto issueB = [&](int pass) {
        uint32_t off = (pass & 1) ? EB1 : EB0;
        #pragma unroll
        for (int i = 0; i < 4; i++) {
            int cell = t + (i << 8);
            int n = cell >> 3, ch = cell & 7;
            const __half* gp = wet + (size_t)(pass * 128 + n) * EDIM + ch * 8;
            cpasync16(sb + (off + n * EP + ch * 4) * 4, gp);
        }
        CP_COMMIT();
    };

    issueB(0);

    if (t < 128) {
        int e = e0 + t;
        ((int*)sm)[EIDX + t] = (e < E) ? __ldg(&src[e]) : 0;
    } else {
        int e = e0 + (t - 128);
        ((int*)sm)[EIDX + t] = (e < E) ? __ldg(&dst[e]) : 0;
    }

    // ea tile load (single fp16): 128 rows x 64 f32
    #pragma unroll
    for (int i = 0; i < 8; i++) {
        int idx = t + (i << 8);
        int row = idx >> 4, f4 = idx & 15;
        int e = e0 + row;
        float4 v = make_float4(0.f, 0.f, 0.f, 0.f);
        if (e < E) v = __ldg(reinterpret_cast<const float4*>(ea + (size_t)e * EDIM + f4 * 4));
        int w = EAH + row * EP + f4 * 2;
        sm[w]     = pack2h(v.x, v.y);
        sm[w + 1] = pack2h(v.z, v.w);
    }

    int arow = wm * 32 + lr + 8 * lm1;
    int brow = wn * 64 + lr + 8 * lm2;
    float* stg = reinterpret_cast<float*>(sm + ESTG) + warp * (16 * 68);
    int r2 = lane >> 4, ch16 = lane & 15;   // epilogue lane map: 2 rows x 16 col-chunks

    #pragma unroll 1
    for (int pass = 0; pass < 4; pass++) {
        if (pass == 3) CP_WAIT0(); else CP_WAIT1();
        __syncthreads();
        if (pass + 1 < 4) issueB(pass + 1);
        uint32_t eb = (pass & 1) ? EB1 : EB0;

        float acc[2][8][4];
        #pragma unroll
        for (int mf = 0; mf < 2; mf++)
            #pragma unroll
            for (int nf = 0; nf < 8; nf++)
                #pragma unroll
                for (int r = 0; r < 4; r++) acc[mf][nf][r] = 0.0f;

        #pragma unroll
        for (int ks = 0; ks < 4; ks++) {
            uint32_t af[2][4], bb[8][2];
            #pragma unroll
            for (int mf = 0; mf < 2; mf++)
                ldm_x4(af[mf], sb + (EAH + (arow + mf * 16) * EP + ks * 8 + 4 * lm2) * 4);
            #pragma unroll
            for (int np = 0; np < 4; np++) {
                uint32_t r[4];
                ldm_x4(r, sb + (eb + (brow + np * 16) * EP + ks * 8 + 4 * lm1) * 4);
                bb[np * 2][0] = r[0]; bb[np * 2][1] = r[1];
                bb[np * 2 + 1][0] = r[2]; bb[np * 2 + 1][1] = r[3];
            }
            #pragma unroll
            for (int mf = 0; mf < 2; mf++)
                #pragma unroll
                for (int nf = 0; nf < 8; nf++)
                    mma_f16(acc[mf][nf], af[mf], bb[nf]);
        }

        // epilogue: stage -> coalesced gather x -> relu -> RED.v4
        int cg2 = pass * 128 + wn * 64;
        float4 bv4 = __ldg(reinterpret_cast<const float4*>(be + cg2) + ch16);

        #pragma unroll
        for (int mf = 0; mf < 2; mf++) {
            __syncwarp();
            #pragma unroll
            for (int nf = 0; nf < 8; nf++)
                #pragma unroll
                for (int h = 0; h < 2; h++) {
                    float2 o;
                    o.x = acc[mf][nf][2 * h];
                    o.y = acc[mf][nf][2 * h + 1];
                    *reinterpret_cast<float2*>(&stg[(g + 8 * h) * 68 + nf * 8 + 2 * qt]) = o;
                }
            __syncwarp();
            #pragma unroll
            for (int it = 0; it < 8; it++) {
                int rloc = it * 2 + r2;
                int loc = wm * 32 + mf * 16 + rloc;
                int e = e0 + loc;
                if (e < E) {
                    int s = ((int*)sm)[EIDX + loc];
                    int d = ((int*)sm)[EIDX + 128 + loc];
                    float4 m4 = *reinterpret_cast<const float4*>(stg + rloc * 68 + ch16 * 4);
                    float4 xv = __ldg(reinterpret_cast<const float4*>(x + (size_t)s * HID + cg2) + ch16);
                    float r0 = fmaxf(m4.x + xv.x + bv4.x, 0.f);
                    float r1 = fmaxf(m4.y + xv.y + bv4.y, 0.f);
                    float r2f = fmaxf(m4.z + xv.z + bv4.z, 0.f);
                    float r3 = fmaxf(m4.w + xv.w + bv4.w, 0.f);
                    float* ar = aggr + (size_t)d * HID + cg2 + ch16 * 4;
                    asm volatile("red.global.add.v4.f32 [%0], {%1,%2,%3,%4};"
                                 :: "l"(ar), "f"(r0), "f"(r1), "f"(r2f), "f"(r3) : "memory");
                }
            }
        }
    }
}

// ---------------------------------------------------------------------------
// Pure-DMA fp16 A-split (2x) HMMA GEMM, triple-buffered cp.async ring.
#define GP 20
#define GAH 0
#define GAL 2560
#define GBH 5120
#define GBUF 7680
#define GSTAT (3 * GBUF)
#define GEMM_SMEM_BYTES ((3 * GBUF + 256) * 4)   // 93184

__global__ void __launch_bounds__(256, 2) mma_gemm(
    const __half* __restrict__ Ah, const __half* __restrict__ Al,
    const __half* __restrict__ Bh, const float* __restrict__ bias,
    float* __restrict__ C, float* __restrict__ stats,
    int M, int K, int NC)
{
    extern __shared__ uint32_t sm[];
    uint32_t sb = smem_u32(sm);
    float* sSum = reinterpret_cast<float*>(sm + GSTAT);
    float* sSq  = sSum + 128;

    int t = threadIdx.x, warp = t >> 5, lane = t & 31;
    int wm = warp >> 1, wn = warp & 1;
    int g = lane >> 2, qt = lane & 3;
    int lr = lane & 7, lm1 = (lane >> 3) & 1, lm2 = lane >> 4;
    int bm = blockIdx.y * 128, bn = blockIdx.x * 128;
    int arow = wm * 32 + lr + 8 * lm1;
    int brow = wn * 64 + lr + 8 * lm2;

    float acc[2][8][4];
    #pragma unroll
    for (int mf = 0; mf < 2; mf++)
        #pragma unroll
        for (int nf = 0; nf < 8; nf++)
            #pragma unroll
            for (int r = 0; r < 4; r++) acc[mf][nf][r] = 0.0f;

    auto issue = [&](int kt, int buf) {
        uint32_t b0 = buf * GBUF;
        #pragma unroll
        for (int i = 0; i < 6; i++) {
            int cell = t + (i << 8);
            int reg = cell >> 9;
            int rem = cell & 511;
            int n = rem >> 2, ch = rem & 3;
            const __half* gp;
            uint32_t roff;
            if (reg == 0)      { gp = Ah + (size_t)(bm + n) * K + kt + ch * 8; roff = GAH; }
            else if (reg == 1) { gp = Al + (size_t)(bm + n) * K + kt + ch * 8; roff = GAL; }
            else               { gp = Bh + (size_t)(bn + n) * K + kt + ch * 8; roff = GBH; }
            cpasync16(sb + (b0 + roff + n * GP + ch * 4) * 4, gp);
        }
        CP_COMMIT();
    };

    int S = K / 32;
    issue(0, 0);
    issue(32, 1);

    for (int s = 0; s < S; s++) {
        if (s == S - 1) CP_WAIT0(); else CP_WAIT1();
        __syncthreads();
        if (s + 2 < S) issue((s + 2) * 32, (s + 2) % 3);
        uint32_t b0 = (uint32_t)((s % 3) * GBUF);
        #pragma unroll
        for (int ks = 0; ks < 2; ks++) {
            uint32_t af[2][4], al2[2][4], bb[8][2];
            #pragma unroll
            for (int mf = 0; mf < 2; mf++) {
                ldm_x4(af[mf],  sb + (b0 + GAH + (arow + mf * 16) * GP + ks * 8 + 4 * lm2) * 4);
                ldm_x4(al2[mf], sb + (b0 + GAL + (arow + mf * 16) * GP + ks * 8 + 4 * lm2) * 4);
            }
            #pragma unroll
            for (int np = 0; np < 4; np++) {
                uint32_t r[4];
                ldm_x4(r, sb + (b0 + GBH + (brow + np * 16) * GP + ks * 8 + 4 * lm1) * 4);
                bb[np * 2][0] = r[0]; bb[np * 2][1] = r[1];
                bb[np * 2 + 1][0] = r[2]; bb[np * 2 + 1][1] = r[3];
            }
            #pragma unroll
            for (int mf = 0; mf < 2; mf++)
                #pragma unroll
                for (int nf = 0; nf < 8; nf++)
                    mma_f16(acc[mf][nf], af[mf], bb[nf]);    // hi*b
            #pragma unroll
            for (int mf = 0; mf < 2; mf++)
                #pragma unroll
                for (int nf = 0; nf < 8; nf++)
                    mma_f16(acc[mf][nf], al2[mf], bb[nf]);   // lo*b
        }
    }

    // Epilogue: bias, store, column stats
    __syncthreads();
    if (t < 128) { sSum[t] = 0.0f; sSq[t] = 0.0f; }
    __syncthreads();

    float2 bv[8];
    #pragma unroll
    for (int nf = 0; nf < 8; nf++)
        bv[nf] = __ldg(reinterpret_cast<const float2*>(bias + bn + wn * 64 + nf * 8 + 2 * qt));

    float colsum[8][2], colsq[8][2];
    #pragma unroll
    for (int nf = 0; nf < 8; nf++) {
        colsum[nf][0] = 0.f; colsum[nf][1] = 0.f;
        colsq[nf][0] = 0.f;  colsq[nf][1] = 0.f;
    }

    #pragma unroll
    for (int mf = 0; mf < 2; mf++)
        #pragma unroll
        for (int half = 0; half < 2; half++) {
            int row = bm + wm * 32 + mf * 16 + g + 8 * half;
            if (row < M) {
                #pragma unroll
                for (int nf = 0; nf < 8; nf++) {
                    float v0 = acc[mf][nf][2 * half]     + bv[nf].x;
                    float v1 = acc[mf][nf][2 * half + 1] + bv[nf].y;
                    colsum[nf][0] += v0; colsq[nf][0] += v0 * v0;
                    colsum[nf][1] += v1; colsq[nf][1] += v1 * v1;
                    float2 o; o.x = v0; o.y = v1;
                    *reinterpret_cast<float2*>(C + (size_t)row * NC + bn + wn * 64 + nf * 8 + 2 * qt) = o;
                }
            }
        }
    #pragma unroll
    for (int nf = 0; nf < 8; nf++) {
        int cb = wn * 64 + nf * 8 + 2 * qt;
        atomicAdd(&sSum[cb],     colsum[nf][0]);
        atomicAdd(&sSum[cb + 1], colsum[nf][1]);
        atomicAdd(&sSq[cb],      colsq[nf][0]);
        atomicAdd(&sSq[cb + 1],  colsq[nf][1]);
    }
    __syncthreads();
    if (t < 128) {
        atomicAdd(&stats[bn + t],      sSum[t]);
        atomicAdd(&stats[NC + bn + t], sSq[t]);
    }
}

// ---------------------------------------------------------------------------
__global__ void bnfin_kernel(const float* __restrict__ stats,
                             const float* __restrict__ g, const float* __restrict__ beta,
                             float* __restrict__ bnp, int NC, float invN)
{
    int c = blockIdx.x * blockDim.x + threadIdx.x;
    if (c < NC) {
        float mu   = stats[c] * invN;
        float var  = stats[NC + c] * invN - mu * mu;
        float rstd = rsqrtf(var + BN_EPS);
        float sc   = g[c] * rstd;
        bnp[c]      = sc;
        bnp[NC + c] = beta[c] - mu * sc;
    }
}

__global__ void bnsilu_kernel(const float* __restrict__ in, float* __restrict__ out,
                              const float* __restrict__ bnp, int c4mask, int nc4, size_t n4)
{
    size_t i = (size_t)blockIdx.x * blockDim.x + threadIdx.x;
    size_t stride = (size_t)gridDim.x * blockDim.x;
    for (; i < n4; i += stride) {
        int c4 = (int)(i & (size_t)c4mask);
        float4 v  = reinterpret_cast<const float4*>(in)[i];
        float4 sc = reinterpret_cast<const float4*>(bnp)[c4];
        float4 sh = reinterpret_cast<const float4*>(bnp)[nc4 + c4];
        float y0 = v.x * sc.x + sh.x;
        float y1 = v.y * sc.y + sh.y;
        float y2 = v.z * sc.z + sh.z;
        float y3 = v.w * sc.w + sh.w;
        float4 r;
        r.x = y0 / (1.0f + __expf(-y0));
        r.y = y1 / (1.0f + __expf(-y1));
        r.z = y2 / (1.0f + __expf(-y2));
        r.w = y3 / (1.0f + __expf(-y3));
        reinterpret_cast<float4*>(out)[i] = r;
    }
}

// ---------------------------------------------------------------------------
extern "C" void kernel_launch(void* const* d_in, const int* in_sizes, int n_in,
                              void* d_out, int out_size)
{
    const float* x     = (const float*)d_in[0];
    const float* ea    = (const float*)d_in[1];
    const int*   ei    = (const int*)d_in[2];
    const float* We    = (const float*)d_in[3];
    const float* be    = (const float*)d_in[4];
    const float* W1    = (const float*)d_in[5];
    const float* b1    = (const float*)d_in[6];
    const float* g1    = (const float*)d_in[7];
    const float* beta1 = (const float*)d_in[8];
    const float* W2    = (const float*)d_in[9];
    const float* b2    = (const float*)d_in[10];
    const float* g2    = (const float*)d_in[11];
    const float* beta2 = (const float*)d_in[12];
    const float* epsp  = (const float*)d_in[13];

    int N = in_sizes[0] / HID;
    int E = in_sizes[1] / EDIM;
    const int* src = ei;
    const int* dst = ei + E;

    float *aggr, *h1, *h2, *stats1, *stats2, *bnp1, *bnp2;
    __half *w1t, *w2t, *wet, *cmbh, *cmbl, *h1sh, *h1sl;
    cudaGetSymbolAddress((void**)&aggr,   g_aggr);
    cudaGetSymbolAddress((void**)&h1,     g_h1);
    cudaGetSymbolAddress((void**)&h2,     g_h2);
    cudaGetSymbolAddress((void**)&stats1, g_stats1);
    cudaGetSymbolAddress((void**)&stats2, g_stats2);
    cudaGetSymbolAddress((void**)&bnp1,   g_bnp1);
    cudaGetSymbolAddress((void**)&bnp2,   g_bnp2);
    cudaGetSymbolAddress((void**)&w1t,    g_w1t);
    cudaGetSymbolAddress((void**)&w2t,    g_w2t);
    cudaGetSymbolAddress((void**)&wet,    g_wet);
    cudaGetSymbolAddress((void**)&cmbh,   g_cmb_hi);
    cudaGetSymbolAddress((void**)&cmbl,   g_cmb_lo);
    cudaGetSymbolAddress((void**)&h1sh,   g_h1s_hi);
    cudaGetSymbolAddress((void**)&h1sl,   g_h1s_lo);

    cudaFuncSetAttribute(edge_mma, cudaFuncAttributeMaxDynamicSharedMemorySize, EDGE_SMEM_BYTES);
    cudaFuncSetAttribute(mma_gemm, cudaFuncAttributeMaxDynamicSharedMemorySize, GEMM_SMEM_BYTES);

    // 0) prep: zero aggr/stats + all weight transposes (one kernel)
    prep_kernel<<<2081, dim3(32, 8)>>>(We, W1, W2, wet, w1t, w2t,
                                       (float4*)aggr, N * HID / 4, stats1, stats2);
    // 1) tensorized edge message + scatter-add
    edge_mma<<<(E + 127) / 128, 256, EDGE_SMEM_BYTES>>>(x, ea, src, dst, wet, be, aggr, E);
    // 2) combine + fp16 split
    combine_split<<<2048, 256>>>((const float4*)x, (const float4*)aggr, epsp,
                                 (uint2*)cmbh, (uint2*)cmbl, N * HID / 4);
    // 3) GEMM1   <-- profiled slot
    {
        dim3 grid((2 * HID) / 128, (N + 127) / 128);
        mma_gemm<<<grid, 256, GEMM_SMEM_BYTES>>>(cmbh, cmbl, w1t, b1, h1, stats1, N, HID, 2 * HID);
    }
    // 4) finalize BN1 params
    bnfin_kernel<<<(2 * HID + 255) / 256, 256>>>(stats1, g1, beta1, bnp1, 2 * HID, 1.0f / N);
    // 5) BN1+SiLU -> fp16 hi/lo
    bnsilu_split<<<2048, 256>>>((const float4*)h1, bnp1, (uint2*)h1sh, (uint2*)h1sl,
                                255, 256, (size_t)N * 2 * HID / 4);
    // 6) GEMM2
    {
        dim3 grid(HID / 128, (N + 127) / 128);
        mma_gemm<<<grid, 256, GEMM_SMEM_BYTES>>>(h1sh, h1sl, w2t, b2, h2, stats2, N, 2 * HID, HID);
    }
    // 7) finalize BN2; 8) final BN + SiLU into d_out
    bnfin_kernel<<<(HID + 255) / 256, 256>>>(stats2, g2, beta2, bnp2, HID, 1.0f / N);
    bnsilu_kernel<<<2048, 256>>>(h2, (float*)d_out, bnp2, 127, 128, (size_t)N * HID / 4);
}

// round 17
// speedup vs baseline: 1.1876x; 1.1604x over previous
#include <cuda_runtime.h>
#include <cuda_fp16.h>
#include <cstdint>
#include <cstddef>

#define HID 512
#define EDIM 64
#define BN_EPS 1e-5f
#define MAXN 50000
#define MAXN2 50048
#define MAXE 400000

// ---------------------------------------------------------------------------
// Scratch (device globals; allocation in kernel_launch is forbidden)
__device__ float g_aggr[MAXN * HID];
__device__ float g_h1[MAXN2 * 2 * HID];
__device__ float g_h2[MAXN * HID];
__device__ float g_stats1[4 * HID];
__device__ float g_stats2[2 * HID];
__device__ float g_bnp1[4 * HID];
__device__ float g_bnp2[2 * HID];
__device__ __half g_w1t[2 * HID * HID];     // [1024][512] K-major fp16
__device__ __half g_w2t[HID * 2 * HID];     // [512][1024] K-major fp16
__device__ __half g_wet[HID * EDIM];        // [512][64]  K-major fp16
__device__ __half g_cmb[MAXN2 * HID];       // GEMM1 A (fp16)
__device__ __half g_h1s[MAXN2 * 2 * HID];   // GEMM2 A (fp16, post BN1+SiLU)

// ---------------------------------------------------------------------------
__device__ __forceinline__ uint32_t smem_u32(const void* p) {
    uint32_t a;
    asm("{ .reg .u64 t; cvta.to.shared.u64 t, %1; cvt.u32.u64 %0, t; }" : "=r"(a) : "l"(p));
    return a;
}
__device__ __forceinline__ uint32_t pack2h(float a, float b) {
    return (uint32_t)__half_as_ushort(__float2half_rn(a))
         | ((uint32_t)__half_as_ushort(__float2half_rn(b)) << 16);
}
__device__ __forceinline__ void mma_f16(float c[4], const uint32_t a[4], const uint32_t b[2]) {
    asm volatile(
        "mma.sync.aligned.m16n8k16.row.col.f32.f16.f16.f32 "
        "{%0,%1,%2,%3}, {%4,%5,%6,%7}, {%8,%9}, {%0,%1,%2,%3};\n"
        : "+f"(c[0]), "+f"(c[1]), "+f"(c[2]), "+f"(c[3])
        : "r"(a[0]), "r"(a[1]), "r"(a[2]), "r"(a[3]), "r"(b[0]), "r"(b[1]));
}
__device__ __forceinline__ void ldm_x4(uint32_t r[4], uint32_t addr) {
    asm volatile("ldmatrix.sync.aligned.m8n8.x4.shared.b16 {%0,%1,%2,%3}, [%4];"
        : "=r"(r[0]), "=r"(r[1]), "=r"(r[2]), "=r"(r[3]) : "r"(addr));
}
__device__ __forceinline__ void cpasync16(uint32_t daddr, const void* g) {
    asm volatile("cp.async.cg.shared.global [%0], [%1], 16;" :: "r"(daddr), "l"(g) : "memory");
}
#define CP_COMMIT() asm volatile("cp.async.commit_group;" ::: "memory")
#define CP_WAIT0()  asm volatile("cp.async.wait_group 0;" ::: "memory")
#define CP_WAIT1()  asm volatile("cp.async.wait_group 1;" ::: "memory")
#define CP_WAIT2()  asm volatile("cp.async.wait_group 2;" ::: "memory")

// ---------------------------------------------------------------------------
// prep_kernel: blockIdx-partitioned roles (transposes + zeroing in one launch)
__device__ __forceinline__ void tsplit_tile(const float* __restrict__ W,
                                            __half* __restrict__ hi,
                                            int K, int NC, int bx, int by,
                                            float (*tile)[33])
{
    int k0 = by * 32, n0 = bx * 32;
    int tx = threadIdx.x, ty = threadIdx.y;   // 32 x 8
    #pragma unroll
    for (int i = 0; i < 32; i += 8)
        tile[ty + i][tx] = W[(size_t)(k0 + ty + i) * NC + n0 + tx];
    __syncthreads();
    #pragma unroll
    for (int i = 0; i < 32; i += 8)
        hi[(size_t)(n0 + ty + i) * K + k0 + tx] = __float2half_rn(tile[tx][ty + i]);
}

__global__ void prep_kernel(const float* __restrict__ We, const float* __restrict__ W1,
                            const float* __restrict__ W2,
                            __half* __restrict__ wet, __half* __restrict__ w1t,
                            __half* __restrict__ w2t,
                            float4* __restrict__ aggr, int n4,
                            float* __restrict__ stats1, float* __restrict__ stats2)
{
    __shared__ float tile[32][33];
    int b = blockIdx.x;
    int t = threadIdx.y * 32 + threadIdx.x;
    if (b < 32)        { tsplit_tile(We, wet, EDIM, HID, b & 15, b >> 4, tile); return; }
    b -= 32;
    if (b < 512)       { tsplit_tile(W1, w1t, HID, 2 * HID, b & 31, b >> 5, tile); return; }
    b -= 512;
    if (b < 512)       { tsplit_tile(W2, w2t, 2 * HID, HID, b & 15, b >> 4, tile); return; }
    b -= 512;
    if (b == 0) {
        for (int i = t; i < 4 * HID; i += 256) stats1[i] = 0.0f;
        for (int i = t; i < 2 * HID; i += 256) stats2[i] = 0.0f;
        return;
    }
    b -= 1;
    int nb = gridDim.x - 1057;
    float4 z = make_float4(0.f, 0.f, 0.f, 0.f);
    for (int i = b * 256 + t; i < n4; i += nb * 256) aggr[i] = z;
}

// ---------------------------------------------------------------------------
// combine_h: out = fp16((1+eps)*x + aggr)
__global__ void combine_h(const float4* __restrict__ x, const float4* __restrict__ aggr,
                          const float* __restrict__ epsp, uint2* __restrict__ hi, int n4)
{
    float c1 = 1.0f + __ldg(epsp);
    int i = blockIdx.x * blockDim.x + threadIdx.x;
    int stride = gridDim.x * blockDim.x;
    for (; i < n4; i += stride) {
        float4 xv = x[i], av = aggr[i];
        uint2 hw;
        hw.x = pack2h(c1 * xv.x + av.x, c1 * xv.y + av.y);
        hw.y = pack2h(c1 * xv.z + av.z, c1 * xv.w + av.w);
        hi[i] = hw;
    }
}

// bnsilu_h: out = fp16(silu(in*scale[col]+shift[col]))
__global__ void bnsilu_h(const float4* __restrict__ in, const float* __restrict__ bnp,
                         uint2* __restrict__ hi, int c4mask, int nc4, size_t n4)
{
    size_t i = (size_t)blockIdx.x * blockDim.x + threadIdx.x;
    size_t stride = (size_t)gridDim.x * blockDim.x;
    for (; i < n4; i += stride) {
        int c4 = (int)(i & (size_t)c4mask);
        float4 v  = in[i];
        float4 sc = reinterpret_cast<const float4*>(bnp)[c4];
        float4 sh = reinterpret_cast<const float4*>(bnp)[nc4 + c4];
        float y0 = v.x * sc.x + sh.x, y1 = v.y * sc.y + sh.y;
        float y2 = v.z * sc.z + sh.z, y3 = v.w * sc.w + sh.w;
        float s0 = y0 / (1.0f + __expf(-y0));
        float s1 = y1 / (1.0f + __expf(-y1));
        float s2 = y2 / (1.0f + __expf(-y2));
        float s3 = y3 / (1.0f + __expf(-y3));
        uint2 hw;
        hw.x = pack2h(s0, s1);
        hw.y = pack2h(s2, s3);
        hi[i] = hw;
    }
}

// ---------------------------------------------------------------------------
// Tensorized edge kernel (R13 best): aggr[dst] += relu(x[src] + ea@We + be)
#define EP 36
#define EAH 0
#define EB0 4608
#define EB1 9216
#define EIDX 13824
#define ESTG 14080
#define EDGE_SMEM_BYTES ((14080 + 8 * 16 * 68) * 4)   // 91136

__global__ void __launch_bounds__(256, 2) edge_mma(
    const float* __restrict__ x, const float* __restrict__ ea,
    const int* __restrict__ src, const int* __restrict__ dst,
    const __half* __restrict__ wet,
    const float* __restrict__ be, float* __restrict__ aggr, int E)
{
    extern __shared__ uint32_t sm[];
    uint32_t sb = smem_u32(sm);
    int t = threadIdx.x, warp = t >> 5, lane = t & 31;
    int wm = warp >> 1, wn = warp & 1;
    int g = lane >> 2, qt = lane & 3;
    int lr = lane & 7, lm1 = (lane >> 3) & 1, lm2 = lane >> 4;
    int e0 = blockIdx.x * 128;

    auto issueB = [&](int pass) {
        uint32_t off = (pass & 1) ? EB1 : EB0;
        #pragma unroll
        for (int i = 0; i < 4; i++) {
            int cell = t + (i << 8);
            int n = cell >> 3, ch = cell & 7;
            const __half* gp = wet + (size_t)(pass * 128 + n) * EDIM + ch * 8;
            cpasync16(sb + (off + n * EP + ch * 4) * 4, gp);
        }
        CP_COMMIT();
    };

    issueB(0);

    if (t < 128) {
        int e = e0 + t;
        ((int*)sm)[EIDX + t] = (e < E) ? __ldg(&src[e]) : 0;
    } else {
        int e = e0 + (t - 128);
        ((int*)sm)[EIDX + t] = (e < E) ? __ldg(&dst[e]) : 0;
    }

    #pragma unroll
    for (int i = 0; i < 8; i++) {
        int idx = t + (i << 8);
        int row = idx >> 4, f4 = idx & 15;
        int e = e0 + row;
        float4 v = make_float4(0.f, 0.f, 0.f, 0.f);
        if (e < E) v = __ldg(reinterpret_cast<const float4*>(ea + (size_t)e * EDIM + f4 * 4));
        int w = EAH + row * EP + f4 * 2;
        sm[w]     = pack2h(v.x, v.y);
        sm[w + 1] = pack2h(v.z, v.w);
    }

    int arow = wm * 32 + lr + 8 * lm1;
    int brow = wn * 64 + lr + 8 * lm2;
    float* stg = reinterpret_cast<float*>(sm + ESTG) + warp * (16 * 68);
    int r2 = lane >> 4, ch16 = lane & 15;

    #pragma unroll 1
    for (int pass = 0; pass < 4; pass++) {
        if (pass == 3) CP_WAIT0(); else CP_WAIT1();
        __syncthreads();
        if (pass + 1 < 4) issueB(pass + 1);
        uint32_t eb = (pass & 1) ? EB1 : EB0;

        float acc[2][8][4];
        #pragma unroll
        for (int mf = 0; mf < 2; mf++)
            #pragma unroll
            for (int nf = 0; nf < 8; nf++)
                #pragma unroll
                for (int r = 0; r < 4; r++) acc[mf][nf][r] = 0.0f;

        #pragma unroll
        for (int ks = 0; ks < 4; ks++) {
            uint32_t af[2][4], bb[8][2];
            #pragma unroll
            for (int mf = 0; mf < 2; mf++)
                ldm_x4(af[mf], sb + (EAH + (arow + mf * 16) * EP + ks * 8 + 4 * lm2) * 4);
            #pragma unroll
            for (int np = 0; np < 4; np++) {
                uint32_t r[4];
                ldm_x4(r, sb + (eb + (brow + np * 16) * EP + ks * 8 + 4 * lm1) * 4);
                bb[np * 2][0] = r[0]; bb[np * 2][1] = r[1];
                bb[np * 2 + 1][0] = r[2]; bb[np * 2 + 1][1] = r[3];
            }
            #pragma unroll
            for (int mf = 0; mf < 2; mf++)
                #pragma unroll
                for (int nf = 0; nf < 8; nf++)
                    mma_f16(acc[mf][nf], af[mf], bb[nf]);
        }

        int cg2 = pass * 128 + wn * 64;
        float4 bv4 = __ldg(reinterpret_cast<const float4*>(be + cg2) + ch16);

        #pragma unroll
        for (int mf = 0; mf < 2; mf++) {
            __syncwarp();
            #pragma unroll
            for (int nf = 0; nf < 8; nf++)
                #pragma unroll
                for (int h = 0; h < 2; h++) {
                    float2 o;
                    o.x = acc[mf][nf][2 * h];
                    o.y = acc[mf][nf][2 * h + 1];
                    *reinterpret_cast<float2*>(&stg[(g + 8 * h) * 68 + nf * 8 + 2 * qt]) = o;
                }
            __syncwarp();
            #pragma unroll
            for (int it = 0; it < 8; it++) {
                int rloc = it * 2 + r2;
                int loc = wm * 32 + mf * 16 + rloc;
                int e = e0 + loc;
                if (e < E) {
                    int s = ((int*)sm)[EIDX + loc];
                    int d = ((int*)sm)[EIDX + 128 + loc];
                    float4 m4 = *reinterpret_cast<const float4*>(stg + rloc * 68 + ch16 * 4);
                    float4 xv = __ldg(reinterpret_cast<const float4*>(x + (size_t)s * HID + cg2) + ch16);
                    float r0 = fmaxf(m4.x + xv.x + bv4.x, 0.f);
                    float r1 = fmaxf(m4.y + xv.y + bv4.y, 0.f);
                    float r2f = fmaxf(m4.z + xv.z + bv4.z, 0.f);
                    float r3 = fmaxf(m4.w + xv.w + bv4.w, 0.f);
                    float* ar = aggr + (size_t)d * HID + cg2 + ch16 * 4;
                    asm volatile("red.global.add.v4.f32 [%0], {%1,%2,%3,%4};"
                                 :: "l"(ar), "f"(r0), "f"(r1), "f"(r2f), "f"(r3) : "memory");
                }
            }
        }
    }
}

// ---------------------------------------------------------------------------
// Single-fp16 HMMA GEMM, depth-4 cp.async ring (3 stages in flight).
#define GP 20
#define GA 0
#define GB 2560
#define GBUF 5120
#define GSTAT (4 * GBUF)
#define GEMM_SMEM_BYTES ((4 * GBUF + 256) * 4)   // 82944

__global__ void __launch_bounds__(256, 2) mma_gemm(
    const __half* __restrict__ Ah, const __half* __restrict__ Bh,
    const float* __restrict__ bias,
    float* __restrict__ C, float* __restrict__ stats,
    int M, int K, int NC)
{
    extern __shared__ uint32_t sm[];
    uint32_t sb = smem_u32(sm);
    float* sSum = reinterpret_cast<float*>(sm + GSTAT);
    float* sSq  = sSum + 128;

    int t = threadIdx.x, warp = t >> 5, lane = t & 31;
    int wm = warp >> 1, wn = warp & 1;
    int g = lane >> 2, qt = lane & 3;
    int lr = lane & 7, lm1 = (lane >> 3) & 1, lm2 = lane >> 4;
    int bm = blockIdx.y * 128, bn = blockIdx.x * 128;
    int arow = wm * 32 + lr + 8 * lm1;
    int brow = wn * 64 + lr + 8 * lm2;

    float acc[2][8][4];
    #pragma unroll
    for (int mf = 0; mf < 2; mf++)
        #pragma unroll
        for (int nf = 0; nf < 8; nf++)
            #pragma unroll
            for (int r = 0; r < 4; r++) acc[mf][nf][r] = 0.0f;

    // stage = A 512 + B 512 cells of 16B = 4 x 256 threads
    auto issue = [&](int kt, int buf) {
        uint32_t b0 = buf * GBUF;
        #pragma unroll
        for (int i = 0; i < 4; i++) {
            int cell = t + (i << 8);
            int reg = cell >> 9;          // 0=A, 1=B
            int rem = cell & 511;
            int n = rem >> 2, ch = rem & 3;
            const __half* gp = reg ? (Bh + (size_t)(bn + n) * K + kt + ch * 8)
                                   : (Ah + (size_t)(bm + n) * K + kt + ch * 8);
            cpasync16(sb + (b0 + (reg ? GB : GA) + n * GP + ch * 4) * 4, gp);
        }
        CP_COMMIT();
    };

    int S = K / 32;
    issue(0, 0);
    issue(32, 1);
    issue(64, 2);

    for (int s = 0; s < S; s++) {
        if (s < S - 2) CP_WAIT2();
        else if (s == S - 2) CP_WAIT1();
        else CP_WAIT0();
        __syncthreads();
        if (s + 3 < S) issue((s + 3) * 32, (s + 3) & 3);
        uint32_t b0 = (uint32_t)((s & 3) * GBUF);
        #pragma unroll
        for (int ks = 0; ks < 2; ks++) {
            uint32_t af[2][4], bb[8][2];
            #pragma unroll
            for (int mf = 0; mf < 2; mf++)
                ldm_x4(af[mf], sb + (b0 + GA + (arow + mf * 16) * GP + ks * 8 + 4 * lm2) * 4);
            #pragma unroll
            for (int np = 0; np < 4; np++) {
                uint32_t r[4];
                ldm_x4(r, sb + (b0 + GB + (brow + np * 16) * GP + ks * 8 + 4 * lm1) * 4);
                bb[np * 2][0] = r[0]; bb[np * 2][1] = r[1];
                bb[np * 2 + 1][0] = r[2]; bb[np * 2 + 1][1] = r[3];
            }
            #pragma unroll
            for (int mf = 0; mf < 2; mf++)
                #pragma unroll
                for (int nf = 0; nf < 8; nf++)
                    mma_f16(acc[mf][nf], af[mf], bb[nf]);
        }
    }

    // Epilogue: bias, store, column stats
    __syncthreads();
    if (t < 128) { sSum[t] = 0.0f; sSq[t] = 0.0f; }
    __syncthreads();

    float2 bv[8];
    #pragma unroll
    for (int nf = 0; nf < 8; nf++)
        bv[nf] = __ldg(reinterpret_cast<const float2*>(bias + bn + wn * 64 + nf * 8 + 2 * qt));

    float colsum[8][2], colsq[8][2];
    #pragma unroll
    for (int nf = 0; nf < 8; nf++) {
        colsum[nf][0] = 0.f; colsum[nf][1] = 0.f;
        colsq[nf][0] = 0.f;  colsq[nf][1] = 0.f;
    }

    #pragma unroll
    for (int mf = 0; mf < 2; mf++)
        #pragma unroll
        for (int half = 0; half < 2; half++) {
            int row = bm + wm * 32 + mf * 16 + g + 8 * half;
            if (row < M) {
                #pragma unroll
                for (int nf = 0; nf < 8; nf++) {
                    float v0 = acc[mf][nf][2 * half]     + bv[nf].x;
                    float v1 = acc[mf][nf][2 * half + 1] + bv[nf].y;
                    colsum[nf][0] += v0; colsq[nf][0] += v0 * v0;
                    colsum[nf][1] += v1; colsq[nf][1] += v1 * v1;
                    float2 o; o.x = v0; o.y = v1;
                    *reinterpret_cast<float2*>(C + (size_t)row * NC + bn + wn * 64 + nf * 8 + 2 * qt) = o;
                }
            }
        }
    #pragma unroll
    for (int nf = 0; nf < 8; nf++) {
        int cb = wn * 64 + nf * 8 + 2 * qt;
        atomicAdd(&sSum[cb],     colsum[nf][0]);
        atomicAdd(&sSum[cb + 1], colsum[nf][1]);
        atomicAdd(&sSq[cb],      colsq[nf][0]);
        atomicAdd(&sSq[cb + 1],  colsq[nf][1]);
    }
    __syncthreads();
    if (t < 128) {
        atomicAdd(&stats[bn + t],      sSum[t]);
        atomicAdd(&stats[NC + bn + t], sSq[t]);
    }
}

// ---------------------------------------------------------------------------
__global__ void bnfin_kernel(const float* __restrict__ stats,
                             const float* __restrict__ g, const float* __restrict__ beta,
                             float* __restrict__ bnp, int NC, float invN)
{
    int c = blockIdx.x * blockDim.x + threadIdx.x;
    if (c < NC) {
        float mu   = stats[c] * invN;
        float var  = stats[NC + c] * invN - mu * mu;
        float rstd = rsqrtf(var + BN_EPS);
        float sc   = g[c] * rstd;
        bnp[c]      = sc;
        bnp[NC + c] = beta[c] - mu * sc;
    }
}

__global__ void bnsilu_kernel(const float* __restrict__ in, float* __restrict__ out,
                              const float* __restrict__ bnp, int c4mask, int nc4, size_t n4)
{
    size_t i = (size_t)blockIdx.x * blockDim.x + threadIdx.x;
    size_t stride = (size_t)gridDim.x * blockDim.x;
    for (; i < n4; i += stride) {
        int c4 = (int)(i & (size_t)c4mask);
        float4 v  = reinterpret_cast<const float4*>(in)[i];
        float4 sc = reinterpret_cast<const float4*>(bnp)[c4];
        float4 sh = reinterpret_cast<const float4*>(bnp)[nc4 + c4];
        float y0 = v.x * sc.x + sh.x;
        float y1 = v.y * sc.y + sh.y;
        float y2 = v.z * sc.z + sh.z;
        float y3 = v.w * sc.w + sh.w;
        float4 r;
        r.x = y0 / (1.0f + __expf(-y0));
        r.y = y1 / (1.0f + __expf(-y1));
        r.z = y2 / (1.0f + __expf(-y2));
        r.w = y3 / (1.0f + __expf(-y3));
        reinterpret_cast<float4*>(out)[i] = r;
    }
}

// ---------------------------------------------------------------------------
extern "C" void kernel_launch(void* const* d_in, const int* in_sizes, int n_in,
                              void* d_out, int out_size)
{
    const float* x     = (const float*)d_in[0];
    const float* ea    = (const float*)d_in[1];
    const int*   ei    = (const int*)d_in[2];
    const float* We    = (const float*)d_in[3];
    const float* be    = (const float*)d_in[4];
    const float* W1    = (const float*)d_in[5];
    const float* b1    = (const float*)d_in[6];
    const float* g1    = (const float*)d_in[7];
    const float* beta1 = (const float*)d_in[8];
    const float* W2    = (const float*)d_in[9];
    const float* b2    = (const float*)d_in[10];
    const float* g2    = (const float*)d_in[11];
    const float* beta2 = (const float*)d_in[12];
    const float* epsp  = (const float*)d_in[13];

    int N = in_sizes[0] / HID;
    int E = in_sizes[1] / EDIM;
    const int* src = ei;
    const int* dst = ei + E;

    float *aggr, *h1, *h2, *stats1, *stats2, *bnp1, *bnp2;
    __half *w1t, *w2t, *wet, *cmb, *h1s;
    cudaGetSymbolAddress((void**)&aggr,   g_aggr);
    cudaGetSymbolAddress((void**)&h1,     g_h1);
    cudaGetSymbolAddress((void**)&h2,     g_h2);
    cudaGetSymbolAddress((void**)&stats1, g_stats1);
    cudaGetSymbolAddress((void**)&stats2, g_stats2);
    cudaGetSymbolAddress((void**)&bnp1,   g_bnp1);
    cudaGetSymbolAddress((void**)&bnp2,   g_bnp2);
    cudaGetSymbolAddress((void**)&w1t,    g_w1t);
    cudaGetSymbolAddress((void**)&w2t,    g_w2t);
    cudaGetSymbolAddress((void**)&wet,    g_wet);
    cudaGetSymbolAddress((void**)&cmb,    g_cmb);
    cudaGetSymbolAddress((void**)&h1s,    g_h1s);

    cudaFuncSetAttribute(edge_mma, cudaFuncAttributeMaxDynamicSharedMemorySize, EDGE_SMEM_BYTES);
    cudaFuncSetAttribute(mma_gemm, cudaFuncAttributeMaxDynamicSharedMemorySize, GEMM_SMEM_BYTES);

    // 0) prep: zero aggr/stats + all weight transposes (one kernel)
    prep_kernel<<<2081, dim3(32, 8)>>>(We, W1, W2, wet, w1t, w2t,
                                       (float4*)aggr, N * HID / 4, stats1, stats2);
    // 1) tensorized edge message + scatter-add
    edge_mma<<<(E + 127) / 128, 256, EDGE_SMEM_BYTES>>>(x, ea, src, dst, wet, be, aggr, E);
    // 2) combine -> fp16
    combine_h<<<2048, 256>>>((const float4*)x, (const float4*)aggr, epsp,
                             (uint2*)cmb, N * HID / 4);
    // 3) GEMM1   <-- profiled slot
    {
        dim3 grid((2 * HID) / 128, (N + 127) / 128);
        mma_gemm<<<grid, 256, GEMM_SMEM_BYTES>>>(cmb, w1t, b1, h1, stats1, N, HID, 2 * HID);
    }
    // 4) finalize BN1 params
    bnfin_kernel<<<(2 * HID + 255) / 256, 256>>>(stats1, g1, beta1, bnp1, 2 * HID, 1.0f / N);
    // 5) BN1+SiLU -> fp16
    bnsilu_h<<<2048, 256>>>((const float4*)h1, bnp1, (uint2*)h1s,
                            255, 256, (size_t)N * 2 * HID / 4);
    // 6) GEMM2
    {
        dim3 grid(HID / 128, (N + 127) / 128);
        mma_gemm<<<grid, 256, GEMM_SMEM_BYTES>>>(h1s, w2t, b2, h2, stats2, N, 2 * HID, HID);
    }
    // 7) finalize BN2; 8) final BN + SiLU into d_out
    bnfin_kernel<<<(HID + 255) / 256, 256>>>(stats2, g2, beta2, bnp2, HID, 1.0f / N);
    bnsilu_kernel<<<2048, 256>>>(h2, (float*)d_out, bnp2, 127, 128, (size_t)N * HID / 4);
}